// round 6
// baseline (speedup 1.0000x reference)
#include <cuda_runtime.h>
#include <cstdint>

#define NL    8
#define NPOS  1024
#define DM    768
#define FT    4096
#define NPAIR 36
#define NT    256

// ---------------------------------------------------------------------------
// Static device scratch
// ---------------------------------------------------------------------------
__device__ float g_xr  [(size_t)NL * NPOS * DM];        //  25 MB  rounded x
__device__ float g_wer [(size_t)NL * FT * DM];          // 100 MB  rounded W_enc
__device__ float g_wdT [(size_t)NPAIR * DM * FT];       // 453 MB  rounded+transposed W_dec [p][d][f]
__device__ float g_feats[(size_t)NL * NPOS * FT];       // 134 MB  feats (tf32-rounded)
__device__ float g_part[(size_t)NPAIR * NPOS * DM];     // 113 MB  decode partials

// ---------------------------------------------------------------------------
// Helpers
// ---------------------------------------------------------------------------
__device__ __forceinline__ unsigned f2tf(float x) {
    unsigned r;
    asm("cvt.rna.tf32.f32 %0, %1;" : "=r"(r) : "f"(x));
    return r;
}
__device__ __forceinline__ uint32_t smem_u32(const void* p) {
    uint32_t a;
    asm("{ .reg .u64 t; cvta.to.shared.u64 t, %1; cvt.u32.u64 %0, t; }" : "=r"(a) : "l"(p));
    return a;
}
#define CP_ASYNC16(dst, src) \
    asm volatile("cp.async.cg.shared.global [%0], [%1], 16;" :: "r"(dst), "l"(src))
#define CP_COMMIT() asm volatile("cp.async.commit_group;" ::: "memory")
#define CP_WAIT2()  asm volatile("cp.async.wait_group 2;" ::: "memory")

__device__ __forceinline__ void mma_tf32(float c[4],
                                         unsigned a0, unsigned a1, unsigned a2, unsigned a3,
                                         unsigned b0, unsigned b1) {
    asm volatile(
        "mma.sync.aligned.m16n8k8.row.col.f32.tf32.tf32.f32 "
        "{%0,%1,%2,%3}, {%4,%5,%6,%7}, {%8,%9}, {%0,%1,%2,%3};"
        : "+f"(c[0]), "+f"(c[1]), "+f"(c[2]), "+f"(c[3])
        : "r"(a0), "r"(a1), "r"(a2), "r"(a3), "r"(b0), "r"(b1));
}
// four 8x8(b16) matrices = one 16x8(b32) tf32 fragment quadrant set
__device__ __forceinline__ void ldsm4(unsigned r[4], uint32_t addr) {
    asm volatile("ldmatrix.sync.aligned.m8n8.x4.shared.b16 {%0,%1,%2,%3}, [%4];"
        : "=r"(r[0]), "=r"(r[1]), "=r"(r[2]), "=r"(r[3]) : "r"(addr));
}

// ---------------------------------------------------------------------------
// SMEM: 4 stages; A tile 256x32 (stride 36 floats), B tile 128x32 (stride 36)
// Both tiles row(=m/n)-major, K contiguous -> ldmatrix-compatible.
// ---------------------------------------------------------------------------
#define STAGES 4
#define ASTR  36
#define A_BYTES (256 * ASTR * 4)         // 36864
#define B_OFF   A_BYTES
#define B_BYTES (128 * ASTR * 4)         // 18432
#define STAGE   (A_BYTES + B_BYTES)      // 55296
#define SMEM_BYTES (STAGES * STAGE)      // 221184

__device__ __forceinline__ void loadA(const float* __restrict__ src, size_t gstr,
                                      uint32_t dst, int tid) {
#pragma unroll
    for (int q = 0; q < 8; q++) {
        int idx = tid + q * NT;
        int row = idx >> 3, seg = idx & 7;
        CP_ASYNC16(dst + (row * ASTR + seg * 4) * 4, src + (size_t)row * gstr + seg * 4);
    }
}
__device__ __forceinline__ void loadB(const float* __restrict__ src, size_t gstr,
                                      uint32_t dst, int tid) {
#pragma unroll
    for (int q = 0; q < 4; q++) {
        int idx = tid + q * NT;
        int row = idx >> 3, seg = idx & 7;
        CP_ASYNC16(dst + (row * ASTR + seg * 4) * 4, src + (size_t)row * gstr + seg * 4);
    }
}

// compute one K=32 chunk; warp tile 64(M) x 64(N); all fragments via ldmatrix.
// lm_off (b32 units): (lane&15)*ASTR + (lane>>4)*4
__device__ __forceinline__ void compute_chunk(uint32_t sA, uint32_t sB, int lm_off,
                                              int wm, int wn, float acc[4][8][4]) {
#pragma unroll
    for (int kk = 0; kk < 4; kk++) {
        const int kb = kk * 8;
        unsigned a[4][4], b[4][4];
#pragma unroll
        for (int mf = 0; mf < 4; mf++)
            ldsm4(a[mf], sA + (((wm * 64 + mf * 16) * ASTR) + kb + lm_off) * 4);
#pragma unroll
        for (int np = 0; np < 4; np++)
            ldsm4(b[np], sB + (((wn * 64 + np * 16) * ASTR) + kb + lm_off) * 4);
        // b[np] = { b(2np)[0], b(2np+1)[0], b(2np)[1], b(2np+1)[1] }
#pragma unroll
        for (int mf = 0; mf < 4; mf++)
#pragma unroll
            for (int np = 0; np < 4; np++) {
                mma_tf32(acc[mf][2 * np],     a[mf][0], a[mf][1], a[mf][2], a[mf][3],
                         b[np][0], b[np][2]);
                mma_tf32(acc[mf][2 * np + 1], a[mf][0], a[mf][1], a[mf][2], a[mf][3],
                         b[np][1], b[np][3]);
            }
    }
}

// ---------------------------------------------------------------------------
// Prep kernels
// ---------------------------------------------------------------------------
__global__ void round_copy(const float* __restrict__ src, float* __restrict__ dst) {
    size_t i = ((size_t)blockIdx.x * 256 + threadIdx.x) * 4;
    float4 v = *(const float4*)(src + i);
    uint4 o = { f2tf(v.x), f2tf(v.y), f2tf(v.z), f2tf(v.w) };
    *(uint4*)(dst + i) = o;
}
// round + transpose: W_dec[i,j][f][d] -> g_wdT[p][d][f]
__global__ void round_wdec_T(const float* __restrict__ W_dec) {
    int p = blockIdx.z;
    int j = 0, a = 0;
    while (a + j + 1 <= p) { a += j + 1; ++j; }
    int i = p - a;
    int f0 = blockIdx.x * 32, d0 = blockIdx.y * 32;
    int tx = threadIdx.x, ty = threadIdx.y;
    __shared__ float t[32][33];
    const float* src = W_dec + (size_t)(i * NL + j) * FT * DM;
#pragma unroll
    for (int r = 0; r < 4; r++)
        t[ty + r * 8][tx] = src[(size_t)(f0 + ty + r * 8) * DM + d0 + tx];
    __syncthreads();
    float* dst = g_wdT + (size_t)p * DM * FT;
#pragma unroll
    for (int r = 0; r < 4; r++)
        dst[(size_t)(d0 + ty + r * 8) * FT + f0 + tx] =
            __uint_as_float(f2tf(t[tx][ty + r * 8]));
}

// ---------------------------------------------------------------------------
// Encoder: feats = relu(x @ W_enc^T + b_enc). grid (FT/128, NPOS/256, NL)
// ---------------------------------------------------------------------------
__global__ __launch_bounds__(NT, 1)
void encode_tc(const float* __restrict__ b_enc) {
    extern __shared__ float smem[];
    const int l = blockIdx.z, m0 = blockIdx.y * 256, n0 = blockIdx.x * 128;
    const int tid = threadIdx.x, lane = tid & 31, warp = tid >> 5;
    const int wm = warp & 3, wn = warp >> 2;
    const uint32_t sb = smem_u32(smem);
    const int lm_off = (lane & 15) * ASTR + (lane >> 4) * 4;

    float acc[4][8][4];
#pragma unroll
    for (int a = 0; a < 4; a++)
#pragma unroll
        for (int b = 0; b < 8; b++)
#pragma unroll
            for (int c = 0; c < 4; c++) acc[a][b][c] = 0.f;

    const float* abase = g_xr  + ((size_t)l * NPOS + m0) * DM;
    const float* bbase = g_wer + ((size_t)l * FT + n0) * DM;
    const int NC = DM / 32;

#pragma unroll
    for (int s = 0; s < STAGES - 1; s++) {
        loadA(abase + s * 32, DM, sb + s * STAGE, tid);
        loadB(bbase + s * 32, DM, sb + s * STAGE + B_OFF, tid);
        CP_COMMIT();
    }
    for (int c = 0; c < NC; c++) {
        CP_WAIT2();
        __syncthreads();
        int nc = c + STAGES - 1;
        if (nc < NC) {
            uint32_t s = sb + (nc & 3) * STAGE;
            loadA(abase + nc * 32, DM, s, tid);
            loadB(bbase + nc * 32, DM, s + B_OFF, tid);
        }
        CP_COMMIT();
        uint32_t st = sb + (c & 3) * STAGE;
        compute_chunk(st, st + B_OFF, lm_off, wm, wn, acc);
    }

    // epilogue: bias + relu + tf32 round -> g_feats
    const float* be = b_enc + (size_t)l * FT + n0;
#pragma unroll
    for (int mf = 0; mf < 4; mf++) {
        int r0 = m0 + wm * 64 + mf * 16 + (lane >> 2);
        float* d0 = g_feats + ((size_t)l * NPOS + r0) * FT + n0;
        float* d1 = d0 + 8 * FT;
#pragma unroll
        for (int nf = 0; nf < 8; nf++) {
            int c0 = wn * 64 + nf * 8 + (lane & 3) * 2;
            float b0 = be[c0], b1 = be[c0 + 1];
            uint2 v0 = { f2tf(fmaxf(acc[mf][nf][0] + b0, 0.f)),
                         f2tf(fmaxf(acc[mf][nf][1] + b1, 0.f)) };
            uint2 v1 = { f2tf(fmaxf(acc[mf][nf][2] + b0, 0.f)),
                         f2tf(fmaxf(acc[mf][nf][3] + b1, 0.f)) };
            *(uint2*)(d0 + c0) = v0;
            *(uint2*)(d1 + c0) = v1;
        }
    }
}

// ---------------------------------------------------------------------------
// Decoder partials: g_part[p] = feats[i] @ W_dec[i,j]. grid (DM/128, NPOS/256, NPAIR)
// ---------------------------------------------------------------------------
__global__ __launch_bounds__(NT, 1)
void decode_tc() {
    extern __shared__ float smem[];
    const int p = blockIdx.z, m0 = blockIdx.y * 256, n0 = blockIdx.x * 128;
    int j = 0, a0 = 0;
    while (a0 + j + 1 <= p) { a0 += j + 1; ++j; }
    const int i = p - a0;
    const int tid = threadIdx.x, lane = tid & 31, warp = tid >> 5;
    const int wm = warp & 3, wn = warp >> 2;
    const uint32_t sb = smem_u32(smem);
    const int lm_off = (lane & 15) * ASTR + (lane >> 4) * 4;

    float acc[4][8][4];
#pragma unroll
    for (int a = 0; a < 4; a++)
#pragma unroll
        for (int b = 0; b < 8; b++)
#pragma unroll
            for (int c = 0; c < 4; c++) acc[a][b][c] = 0.f;

    const float* abase = g_feats + ((size_t)i * NPOS + m0) * FT;
    const float* bbase = g_wdT + (size_t)p * DM * FT + (size_t)n0 * FT;
    const int NC = FT / 32;

#pragma unroll
    for (int s = 0; s < STAGES - 1; s++) {
        loadA(abase + s * 32, FT, sb + s * STAGE, tid);
        loadB(bbase + s * 32, FT, sb + s * STAGE + B_OFF, tid);
        CP_COMMIT();
    }
    for (int c = 0; c < NC; c++) {
        CP_WAIT2();
        __syncthreads();
        int nc = c + STAGES - 1;
        if (nc < NC) {
            uint32_t s = sb + (nc & 3) * STAGE;
            loadA(abase + nc * 32, FT, s, tid);
            loadB(bbase + nc * 32, FT, s + B_OFF, tid);
        }
        CP_COMMIT();
        uint32_t st = sb + (c & 3) * STAGE;
        compute_chunk(st, st + B_OFF, lm_off, wm, wn, acc);
    }

    // epilogue -> g_part
#pragma unroll
    for (int mf = 0; mf < 4; mf++) {
        int r0 = m0 + wm * 64 + mf * 16 + (lane >> 2);
        float* d0 = g_part + ((size_t)p * NPOS + r0) * DM + n0;
        float* d1 = d0 + 8 * DM;
#pragma unroll
        for (int nf = 0; nf < 8; nf++) {
            int c0 = wn * 64 + nf * 8 + (lane & 3) * 2;
            float2 v0 = { acc[mf][nf][0], acc[mf][nf][1] };
            float2 v1 = { acc[mf][nf][2], acc[mf][nf][3] };
            *(float2*)(d0 + c0) = v0;
            *(float2*)(d1 + c0) = v1;
        }
    }
}

// ---------------------------------------------------------------------------
// Fixed-order reduction over sources + bias. grid (NPOS*DM/1024, NL)
// ---------------------------------------------------------------------------
__global__ __launch_bounds__(256, 4)
void reduce_out(const float* __restrict__ b_dec, float* __restrict__ out) {
    const int jj = blockIdx.y;
    const int base = jj * (jj + 1) / 2;
    size_t lin = ((size_t)blockIdx.x * 256 + threadIdx.x) * 4;
    int d = (int)(lin % DM);
    float4 acc = *(const float4*)(b_dec + (size_t)jj * DM + d);
    for (int i = 0; i <= jj; i++) {
        float4 v = *(const float4*)(g_part + (size_t)(base + i) * NPOS * DM + lin);
        acc.x += v.x; acc.y += v.y; acc.z += v.z; acc.w += v.w;
    }
    *(float4*)(out + (size_t)jj * NPOS * DM + lin) = acc;
}

// ---------------------------------------------------------------------------
extern "C" void kernel_launch(void* const* d_in, const int* in_sizes, int n_in,
                              void* d_out, int out_size) {
    const float* x     = (const float*)d_in[0];
    const float* W_enc = (const float*)d_in[1];
    const float* b_enc = (const float*)d_in[2];
    const float* W_dec = (const float*)d_in[3];
    const float* b_dec = (const float*)d_in[4];
    float* out = (float*)d_out;

    static cudaStream_t s2 = nullptr;
    static cudaEvent_t evA = nullptr, evB = nullptr;
    if (!s2) {
        cudaFuncSetAttribute(encode_tc, cudaFuncAttributeMaxDynamicSharedMemorySize, SMEM_BYTES);
        cudaFuncSetAttribute(decode_tc, cudaFuncAttributeMaxDynamicSharedMemorySize, SMEM_BYTES);
        cudaStreamCreateWithFlags(&s2, cudaStreamNonBlocking);
        cudaEventCreateWithFlags(&evA, cudaEventDisableTiming);
        cudaEventCreateWithFlags(&evB, cudaEventDisableTiming);
    }

    float* g_xr_p;   cudaGetSymbolAddress((void**)&g_xr_p,  g_xr);
    float* g_wer_p;  cudaGetSymbolAddress((void**)&g_wer_p, g_wer);

    // Fork: W_dec round+transpose on side stream, overlapped with encode chain.
    cudaEventRecord(evA, 0);
    cudaStreamWaitEvent(s2, evA, 0);
    round_wdec_T<<<dim3(FT / 32, DM / 32, NPAIR), dim3(32, 8), 0, s2>>>(W_dec);
    cudaEventRecord(evB, s2);

    round_copy<<<(NL * NPOS * DM) / 1024, 256>>>(x, g_xr_p);
    round_copy<<<(NL * FT * DM) / 1024, 256>>>(W_enc, g_wer_p);
    encode_tc<<<dim3(FT / 128, NPOS / 256, NL), NT, SMEM_BYTES>>>(b_enc);

    // Join, then decode + reduce.
    cudaStreamWaitEvent(0, evB, 0);
    decode_tc<<<dim3(DM / 128, NPOS / 256, NPAIR), NT, SMEM_BYTES>>>();
    reduce_out<<<dim3(NPOS * DM / 1024, NL), 256>>>(b_dec, out);
}

// round 7
// speedup vs baseline: 1.1384x; 1.1384x over previous
#include <cuda_runtime.h>
#include <cstdint>

#define NL    8
#define NPOS  1024
#define DM    768
#define FT    4096
#define NPAIR 36
#define NT    128           // 4 warps per CTA, 2 CTAs per SM

// ---------------------------------------------------------------------------
// Static device scratch
// ---------------------------------------------------------------------------
__device__ float g_xr  [(size_t)NL * NPOS * DM];        //  25 MB  rounded x
__device__ float g_wer [(size_t)NL * FT * DM];          // 100 MB  rounded W_enc
__device__ float g_wdr [(size_t)NPAIR * FT * DM];       // 453 MB  rounded triangular W_dec
__device__ float g_feats[(size_t)NL * NPOS * FT];       // 134 MB  feats (tf32-rounded)
__device__ float g_part[(size_t)NPAIR * NPOS * DM];     // 113 MB  decode partials

// ---------------------------------------------------------------------------
// Helpers
// ---------------------------------------------------------------------------
__device__ __forceinline__ unsigned f2tf(float x) {
    unsigned r;
    asm("cvt.rna.tf32.f32 %0, %1;" : "=r"(r) : "f"(x));
    return r;
}
__device__ __forceinline__ uint32_t smem_u32(const void* p) {
    uint32_t a;
    asm("{ .reg .u64 t; cvta.to.shared.u64 t, %1; cvt.u32.u64 %0, t; }" : "=r"(a) : "l"(p));
    return a;
}
#define CP_ASYNC16(dst, src) \
    asm volatile("cp.async.cg.shared.global [%0], [%1], 16;" :: "r"(dst), "l"(src))
#define CP_COMMIT() asm volatile("cp.async.commit_group;" ::: "memory")
#define CP_WAIT1()  asm volatile("cp.async.wait_group 1;" ::: "memory")

__device__ __forceinline__ void mma_tf32(float c[4],
                                         unsigned a0, unsigned a1, unsigned a2, unsigned a3,
                                         unsigned b0, unsigned b1) {
    asm volatile(
        "mma.sync.aligned.m16n8k8.row.col.f32.tf32.tf32.f32 "
        "{%0,%1,%2,%3}, {%4,%5,%6,%7}, {%8,%9}, {%0,%1,%2,%3};"
        : "+f"(c[0]), "+f"(c[1]), "+f"(c[2]), "+f"(c[3])
        : "r"(a0), "r"(a1), "r"(a2), "r"(a3), "r"(b0), "r"(b1));
}

// ---------------------------------------------------------------------------
// SMEM: 3 stages; A tile 128x32 (stride 36 floats)
//   decode B: 32 x 128 (stride 136 floats); encode B: 128 x 32 (stride 36)
// ---------------------------------------------------------------------------
#define STAGES 3
#define ASTR  36
#define BKSTR 136
#define A_BYTES (128 * ASTR * 4)         // 18432
#define B_OFF   A_BYTES
#define B_BYTES (128 * ASTR * 4)         // 18432 >= 32*136*4 = 17408
#define STAGE   (A_BYTES + B_BYTES)      // 36864
#define SMEM_BYTES (STAGES * STAGE)      // 110592 per CTA (x2 CTAs = 221184)

__device__ __forceinline__ void loadA(const float* __restrict__ src, size_t gstr,
                                      uint32_t dst, int tid) {
#pragma unroll
    for (int q = 0; q < 8; q++) {
        int idx = tid + q * NT;
        int row = idx >> 3, seg = idx & 7;
        CP_ASYNC16(dst + (row * ASTR + seg * 4) * 4, src + (size_t)row * gstr + seg * 4);
    }
}
__device__ __forceinline__ void loadB_kn(const float* __restrict__ src, size_t gstr,
                                         uint32_t dst, int tid) {
#pragma unroll
    for (int q = 0; q < 8; q++) {
        int idx = tid + q * NT;
        int row = idx >> 5, seg = idx & 31;
        CP_ASYNC16(dst + (row * BKSTR + seg * 4) * 4, src + (size_t)row * gstr + seg * 4);
    }
}
__device__ __forceinline__ void loadB_nk(const float* __restrict__ src, size_t gstr,
                                         uint32_t dst, int tid) {
#pragma unroll
    for (int q = 0; q < 8; q++) {
        int idx = tid + q * NT;
        int row = idx >> 3, seg = idx & 7;
        CP_ASYNC16(dst + (row * ASTR + seg * 4) * 4, src + (size_t)row * gstr + seg * 4);
    }
}

// compute one K=32 chunk; warp tile 64(M) x 64(N); 2x2 warp grid.
// B_KN=1: Bs[k][n] (decode); B_KN=0: Bs[n][k] (encode)
template <int B_KN>
__device__ __forceinline__ void compute_chunk(const float* __restrict__ smem, int stage,
                                              int wm, int wn, int lane,
                                              float acc[4][8][4]) {
    const unsigned* As = (const unsigned*)(smem) + stage * (STAGE / 4);
    const unsigned* Bs = As + A_BYTES / 4;
#pragma unroll
    for (int kk = 0; kk < 4; kk++) {
        const int kb = kk * 8;
        unsigned a[4][4], b[8][2];
#pragma unroll
        for (int mf = 0; mf < 4; mf++) {
            int r0 = wm * 64 + mf * 16 + (lane >> 2);
            int kc = kb + (lane & 3);
            a[mf][0] = As[r0 * ASTR + kc];
            a[mf][1] = As[(r0 + 8) * ASTR + kc];
            a[mf][2] = As[r0 * ASTR + kc + 4];
            a[mf][3] = As[(r0 + 8) * ASTR + kc + 4];
        }
#pragma unroll
        for (int nf = 0; nf < 8; nf++) {
            int n = wn * 64 + nf * 8 + (lane >> 2);
            int kc = kb + (lane & 3);
            if (B_KN) {
                b[nf][0] = Bs[kc * BKSTR + n];
                b[nf][1] = Bs[(kc + 4) * BKSTR + n];
            } else {
                b[nf][0] = Bs[n * ASTR + kc];
                b[nf][1] = Bs[n * ASTR + kc + 4];
            }
        }
#pragma unroll
        for (int mf = 0; mf < 4; mf++)
#pragma unroll
            for (int nf = 0; nf < 8; nf++)
                mma_tf32(acc[mf][nf], a[mf][0], a[mf][1], a[mf][2], a[mf][3],
                         b[nf][0], b[nf][1]);
    }
}

// ---------------------------------------------------------------------------
// Prep kernels
// ---------------------------------------------------------------------------
__global__ void round_copy(const float* __restrict__ src, float* __restrict__ dst) {
    size_t i = ((size_t)blockIdx.x * 256 + threadIdx.x) * 4;
    float4 v = *(const float4*)(src + i);
    uint4 o = { f2tf(v.x), f2tf(v.y), f2tf(v.z), f2tf(v.w) };
    *(uint4*)(dst + i) = o;
}
__global__ void round_wdec(const float* __restrict__ W_dec) {
    int p = blockIdx.y;
    int j = 0, a = 0;
    while (a + j + 1 <= p) { a += j + 1; ++j; }
    int i = p - a;
    const float* src = W_dec + (size_t)(i * NL + j) * FT * DM;
    float* dst = g_wdr + (size_t)p * FT * DM;
    size_t e = ((size_t)blockIdx.x * 256 + threadIdx.x) * 4;
    float4 v = *(const float4*)(src + e);
    uint4 o = { f2tf(v.x), f2tf(v.y), f2tf(v.z), f2tf(v.w) };
    *(uint4*)(dst + e) = o;
}

// ---------------------------------------------------------------------------
// Encoder: feats = relu(x @ W_enc^T + b_enc). grid (FT/128, NPOS/128, NL)
// ---------------------------------------------------------------------------
__global__ __launch_bounds__(NT, 2)
void encode_tc(const float* __restrict__ b_enc) {
    extern __shared__ float smem[];
    const int l = blockIdx.z, m0 = blockIdx.y * 128, n0 = blockIdx.x * 128;
    const int tid = threadIdx.x, lane = tid & 31, warp = tid >> 5;
    const int wm = warp & 1, wn = warp >> 1;    // 2 x 2 warp grid
    const uint32_t sb = smem_u32(smem);

    float acc[4][8][4];
#pragma unroll
    for (int a = 0; a < 4; a++)
#pragma unroll
        for (int b = 0; b < 8; b++)
#pragma unroll
            for (int c = 0; c < 4; c++) acc[a][b][c] = 0.f;

    const float* abase = g_xr  + ((size_t)l * NPOS + m0) * DM;
    const float* bbase = g_wer + ((size_t)l * FT + n0) * DM;
    const int NC = DM / 32;

#pragma unroll
    for (int s = 0; s < STAGES - 1; s++) {
        loadA(abase + s * 32, DM, sb + s * STAGE, tid);
        loadB_nk(bbase + s * 32, DM, sb + s * STAGE + B_OFF, tid);
        CP_COMMIT();
    }
    for (int c = 0; c < NC; c++) {
        CP_WAIT1();
        __syncthreads();
        int nc = c + STAGES - 1;
        if (nc < NC) {
            uint32_t s = sb + (nc % STAGES) * STAGE;
            loadA(abase + nc * 32, DM, s, tid);
            loadB_nk(bbase + nc * 32, DM, s + B_OFF, tid);
        }
        CP_COMMIT();
        compute_chunk<0>(smem, c % STAGES, wm, wn, lane, acc);
    }

    // epilogue: bias + relu + tf32 round -> g_feats
    const float* be = b_enc + (size_t)l * FT + n0;
#pragma unroll
    for (int mf = 0; mf < 4; mf++) {
        int r0 = m0 + wm * 64 + mf * 16 + (lane >> 2);
        float* d0 = g_feats + ((size_t)l * NPOS + r0) * FT + n0;
        float* d1 = d0 + 8 * FT;
#pragma unroll
        for (int nf = 0; nf < 8; nf++) {
            int c0 = wn * 64 + nf * 8 + (lane & 3) * 2;
            float b0 = be[c0], b1 = be[c0 + 1];
            uint2 v0 = { f2tf(fmaxf(acc[mf][nf][0] + b0, 0.f)),
                         f2tf(fmaxf(acc[mf][nf][1] + b1, 0.f)) };
            uint2 v1 = { f2tf(fmaxf(acc[mf][nf][2] + b0, 0.f)),
                         f2tf(fmaxf(acc[mf][nf][3] + b1, 0.f)) };
            *(uint2*)(d0 + c0) = v0;
            *(uint2*)(d1 + c0) = v1;
        }
    }
}

// ---------------------------------------------------------------------------
// Decoder partials: g_part[p] = feats[i] @ W_dec[i,j]. grid (DM/128, NPOS/128, NPAIR)
// ---------------------------------------------------------------------------
__global__ __launch_bounds__(NT, 2)
void decode_tc() {
    extern __shared__ float smem[];
    const int p = blockIdx.z, m0 = blockIdx.y * 128, n0 = blockIdx.x * 128;
    int j = 0, a0 = 0;
    while (a0 + j + 1 <= p) { a0 += j + 1; ++j; }
    const int i = p - a0;
    const int tid = threadIdx.x, lane = tid & 31, warp = tid >> 5;
    const int wm = warp & 1, wn = warp >> 1;
    const uint32_t sb = smem_u32(smem);

    float acc[4][8][4];
#pragma unroll
    for (int a = 0; a < 4; a++)
#pragma unroll
        for (int b = 0; b < 8; b++)
#pragma unroll
            for (int c = 0; c < 4; c++) acc[a][b][c] = 0.f;

    const float* abase = g_feats + ((size_t)i * NPOS + m0) * FT;
    const float* bbase = g_wdr + (size_t)p * FT * DM + n0;
    const int NC = FT / 32;

#pragma unroll
    for (int s = 0; s < STAGES - 1; s++) {
        loadA(abase + s * 32, FT, sb + s * STAGE, tid);
        loadB_kn(bbase + (size_t)s * 32 * DM, DM, sb + s * STAGE + B_OFF, tid);
        CP_COMMIT();
    }
    for (int c = 0; c < NC; c++) {
        CP_WAIT1();
        __syncthreads();
        int nc = c + STAGES - 1;
        if (nc < NC) {
            uint32_t s = sb + (nc % STAGES) * STAGE;
            loadA(abase + nc * 32, FT, s, tid);
            loadB_kn(bbase + (size_t)nc * 32 * DM, DM, s + B_OFF, tid);
        }
        CP_COMMIT();
        compute_chunk<1>(smem, c % STAGES, wm, wn, lane, acc);
    }

    // epilogue -> g_part
#pragma unroll
    for (int mf = 0; mf < 4; mf++) {
        int r0 = m0 + wm * 64 + mf * 16 + (lane >> 2);
        float* d0 = g_part + ((size_t)p * NPOS + r0) * DM + n0;
        float* d1 = d0 + 8 * DM;
#pragma unroll
        for (int nf = 0; nf < 8; nf++) {
            int c0 = wn * 64 + nf * 8 + (lane & 3) * 2;
            float2 v0 = { acc[mf][nf][0], acc[mf][nf][1] };
            float2 v1 = { acc[mf][nf][2], acc[mf][nf][3] };
            *(float2*)(d0 + c0) = v0;
            *(float2*)(d1 + c0) = v1;
        }
    }
}

// ---------------------------------------------------------------------------
// Fixed-order reduction over sources + bias. grid (NPOS*DM/1024, NL)
// ---------------------------------------------------------------------------
__global__ __launch_bounds__(256, 4)
void reduce_out(const float* __restrict__ b_dec, float* __restrict__ out) {
    const int jj = blockIdx.y;
    const int base = jj * (jj + 1) / 2;
    size_t lin = ((size_t)blockIdx.x * 256 + threadIdx.x) * 4;
    int d = (int)(lin % DM);
    float4 acc = *(const float4*)(b_dec + (size_t)jj * DM + d);
    for (int i = 0; i <= jj; i++) {
        float4 v = *(const float4*)(g_part + (size_t)(base + i) * NPOS * DM + lin);
        acc.x += v.x; acc.y += v.y; acc.z += v.z; acc.w += v.w;
    }
    *(float4*)(out + (size_t)jj * NPOS * DM + lin) = acc;
}

// ---------------------------------------------------------------------------
extern "C" void kernel_launch(void* const* d_in, const int* in_sizes, int n_in,
                              void* d_out, int out_size) {
    const float* x     = (const float*)d_in[0];
    const float* W_enc = (const float*)d_in[1];
    const float* b_enc = (const float*)d_in[2];
    const float* W_dec = (const float*)d_in[3];
    const float* b_dec = (const float*)d_in[4];
    float* out = (float*)d_out;

    static cudaStream_t s2 = nullptr;
    static cudaEvent_t evA = nullptr, evB = nullptr;
    if (!s2) {
        cudaFuncSetAttribute(encode_tc, cudaFuncAttributeMaxDynamicSharedMemorySize, SMEM_BYTES);
        cudaFuncSetAttribute(decode_tc, cudaFuncAttributeMaxDynamicSharedMemorySize, SMEM_BYTES);
        cudaStreamCreateWithFlags(&s2, cudaStreamNonBlocking);
        cudaEventCreateWithFlags(&evA, cudaEventDisableTiming);
        cudaEventCreateWithFlags(&evB, cudaEventDisableTiming);
    }

    float* g_xr_p;   cudaGetSymbolAddress((void**)&g_xr_p,  g_xr);
    float* g_wer_p;  cudaGetSymbolAddress((void**)&g_wer_p, g_wer);

    // Fork: W_dec rounding on side stream, overlapped with encode chain.
    cudaEventRecord(evA, 0);
    cudaStreamWaitEvent(s2, evA, 0);
    round_wdec<<<dim3((FT * DM) / 1024, NPAIR), 256, 0, s2>>>(W_dec);
    cudaEventRecord(evB, s2);

    round_copy<<<(NL * NPOS * DM) / 1024, 256>>>(x, g_xr_p);
    round_copy<<<(NL * FT * DM) / 1024, 256>>>(W_enc, g_wer_p);
    encode_tc<<<dim3(FT / 128, NPOS / 128, NL), NT, SMEM_BYTES>>>(b_enc);

    // Join, then decode + reduce.
    cudaStreamWaitEvent(0, evB, 0);
    decode_tc<<<dim3(DM / 128, NPOS / 128, NPAIR), NT, SMEM_BYTES>>>();
    reduce_out<<<dim3(NPOS * DM / 1024, NL), 256>>>(b_dec, out);
}

// round 8
// speedup vs baseline: 1.1497x; 1.0099x over previous
#include <cuda_runtime.h>
#include <cstdint>

#define NL    8
#define NPOS  1024
#define DM    768
#define FT    4096
#define NPAIR 36
#define NT    256           // 8 warps, 4x2 warp grid, 64x64 warp tiles

// ---------------------------------------------------------------------------
// Static device scratch
// ---------------------------------------------------------------------------
__device__ float g_xr  [(size_t)NL * NPOS * DM];        //  25 MB  rounded x
__device__ float g_wer [(size_t)NL * FT * DM];          // 100 MB  rounded W_enc
__device__ float g_wdr [(size_t)NPAIR * FT * DM];       // 453 MB  rounded triangular W_dec
__device__ float g_feats[(size_t)NL * NPOS * FT];       // 134 MB  feats (tf32-rounded)
__device__ float g_part[(size_t)NPAIR * NPOS * DM];     // 113 MB  decode partials

// ---------------------------------------------------------------------------
// Helpers
// ---------------------------------------------------------------------------
__device__ __forceinline__ unsigned f2tf(float x) {
    unsigned r;
    asm("cvt.rna.tf32.f32 %0, %1;" : "=r"(r) : "f"(x));
    return r;
}
__device__ __forceinline__ uint32_t smem_u32(const void* p) {
    uint32_t a;
    asm("{ .reg .u64 t; cvta.to.shared.u64 t, %1; cvt.u32.u64 %0, t; }" : "=r"(a) : "l"(p));
    return a;
}
#define CP_ASYNC16(dst, src) \
    asm volatile("cp.async.cg.shared.global [%0], [%1], 16;" :: "r"(dst), "l"(src))
#define CP_COMMIT() asm volatile("cp.async.commit_group;" ::: "memory")
#define CP_WAIT1()  asm volatile("cp.async.wait_group 1;" ::: "memory")

__device__ __forceinline__ void mma_tf32(float c[4],
                                         unsigned a0, unsigned a1, unsigned a2, unsigned a3,
                                         unsigned b0, unsigned b1) {
    asm volatile(
        "mma.sync.aligned.m16n8k8.row.col.f32.tf32.tf32.f32 "
        "{%0,%1,%2,%3}, {%4,%5,%6,%7}, {%8,%9}, {%0,%1,%2,%3};"
        : "+f"(c[0]), "+f"(c[1]), "+f"(c[2]), "+f"(c[3])
        : "r"(a0), "r"(a1), "r"(a2), "r"(a3), "r"(b0), "r"(b1));
}

// ---------------------------------------------------------------------------
// SMEM: 2 stages, K-chunk 64.
//   A tile 256x64 (stride 68 floats)  = 69632 B
//   encode B: 128x64 (stride 68)      = 34816 B
//   decode B: 64x128 (stride 136)     = 34816 B
// ---------------------------------------------------------------------------
#define STAGES 2
#define KC    64
#define ASTR  68
#define BKSTR 136
#define A_BYTES (256 * ASTR * 4)         // 69632
#define B_OFF   A_BYTES
#define B_BYTES (128 * ASTR * 4)         // 34816
#define STAGE   (A_BYTES + B_BYTES)      // 104448
#define SMEM_BYTES (STAGES * STAGE)      // 208896

// A loader: 256 rows x 64 floats (16 float4/row), K-contiguous source
__device__ __forceinline__ void loadA(const float* __restrict__ src, size_t gstr,
                                      uint32_t dst, int tid) {
#pragma unroll
    for (int q = 0; q < 16; q++) {
        int idx = tid + q * NT;
        int row = idx >> 4, seg = idx & 15;
        CP_ASYNC16(dst + (row * ASTR + seg * 4) * 4, src + (size_t)row * gstr + seg * 4);
    }
}
// decode B: 64 k-rows x 128 n-floats (32 float4/row), n-contiguous source
__device__ __forceinline__ void loadB_kn(const float* __restrict__ src, size_t gstr,
                                         uint32_t dst, int tid) {
#pragma unroll
    for (int q = 0; q < 8; q++) {
        int idx = tid + q * NT;
        int row = idx >> 5, seg = idx & 31;
        CP_ASYNC16(dst + (row * BKSTR + seg * 4) * 4, src + (size_t)row * gstr + seg * 4);
    }
}
// encode B: 128 n-rows x 64 k-floats (16 float4/row), K-contiguous source
__device__ __forceinline__ void loadB_nk(const float* __restrict__ src, size_t gstr,
                                         uint32_t dst, int tid) {
#pragma unroll
    for (int q = 0; q < 8; q++) {
        int idx = tid + q * NT;
        int row = idx >> 4, seg = idx & 15;
        CP_ASYNC16(dst + (row * ASTR + seg * 4) * 4, src + (size_t)row * gstr + seg * 4);
    }
}

// compute one K=64 chunk; warp tile 64(M) x 64(N); 4x2 warp grid.
// B_KN=1: Bs[k][n] (decode); B_KN=0: Bs[n][k] (encode)
template <int B_KN>
__device__ __forceinline__ void compute_chunk(const float* __restrict__ smem, int stage,
                                              int wm, int wn, int lane,
                                              float acc[4][8][4]) {
    const unsigned* As = (const unsigned*)(smem) + stage * (STAGE / 4);
    const unsigned* Bs = As + A_BYTES / 4;
#pragma unroll
    for (int kk = 0; kk < 8; kk++) {
        const int kb = kk * 8;
        unsigned a[4][4], b[8][2];
#pragma unroll
        for (int mf = 0; mf < 4; mf++) {
            int r0 = wm * 64 + mf * 16 + (lane >> 2);
            int kc = kb + (lane & 3);
            a[mf][0] = As[r0 * ASTR + kc];
            a[mf][1] = As[(r0 + 8) * ASTR + kc];
            a[mf][2] = As[r0 * ASTR + kc + 4];
            a[mf][3] = As[(r0 + 8) * ASTR + kc + 4];
        }
#pragma unroll
        for (int nf = 0; nf < 8; nf++) {
            int n = wn * 64 + nf * 8 + (lane >> 2);
            int kc = kb + (lane & 3);
            if (B_KN) {
                b[nf][0] = Bs[kc * BKSTR + n];
                b[nf][1] = Bs[(kc + 4) * BKSTR + n];
            } else {
                b[nf][0] = Bs[n * ASTR + kc];
                b[nf][1] = Bs[n * ASTR + kc + 4];
            }
        }
#pragma unroll
        for (int mf = 0; mf < 4; mf++)
#pragma unroll
            for (int nf = 0; nf < 8; nf++)
                mma_tf32(acc[mf][nf], a[mf][0], a[mf][1], a[mf][2], a[mf][3],
                         b[nf][0], b[nf][1]);
    }
}

// ---------------------------------------------------------------------------
// Prep kernels
// ---------------------------------------------------------------------------
__global__ void round_copy(const float* __restrict__ src, float* __restrict__ dst) {
    size_t i = ((size_t)blockIdx.x * 256 + threadIdx.x) * 4;
    float4 v = *(const float4*)(src + i);
    uint4 o = { f2tf(v.x), f2tf(v.y), f2tf(v.z), f2tf(v.w) };
    *(uint4*)(dst + i) = o;
}
__global__ void round_wdec(const float* __restrict__ W_dec) {
    int p = blockIdx.y;
    int j = 0, a = 0;
    while (a + j + 1 <= p) { a += j + 1; ++j; }
    int i = p - a;
    const float* src = W_dec + (size_t)(i * NL + j) * FT * DM;
    float* dst = g_wdr + (size_t)p * FT * DM;
    size_t e = ((size_t)blockIdx.x * 256 + threadIdx.x) * 4;
    float4 v = *(const float4*)(src + e);
    uint4 o = { f2tf(v.x), f2tf(v.y), f2tf(v.z), f2tf(v.w) };
    *(uint4*)(dst + e) = o;
}

// ---------------------------------------------------------------------------
// Encoder: feats = relu(x @ W_enc^T + b_enc). grid (FT/128, NPOS/256, NL)
// ---------------------------------------------------------------------------
__global__ __launch_bounds__(NT, 1)
void encode_tc(const float* __restrict__ b_enc) {
    extern __shared__ float smem[];
    const int l = blockIdx.z, m0 = blockIdx.y * 256, n0 = blockIdx.x * 128;
    const int tid = threadIdx.x, lane = tid & 31, warp = tid >> 5;
    const int wm = warp & 3, wn = warp >> 2;
    const uint32_t sb = smem_u32(smem);

    float acc[4][8][4];
#pragma unroll
    for (int a = 0; a < 4; a++)
#pragma unroll
        for (int b = 0; b < 8; b++)
#pragma unroll
            for (int c = 0; c < 4; c++) acc[a][b][c] = 0.f;

    const float* abase = g_xr  + ((size_t)l * NPOS + m0) * DM;
    const float* bbase = g_wer + ((size_t)l * FT + n0) * DM;
    const int NC = DM / KC;     // 12

    loadA(abase, DM, sb, tid);
    loadB_nk(bbase, DM, sb + B_OFF, tid);
    CP_COMMIT();
    for (int c = 0; c < NC; c++) {
        int nc = c + 1;
        if (nc < NC) {
            uint32_t s = sb + (nc & 1) * STAGE;
            if (c > 0) { CP_WAIT1(); __syncthreads(); }
            loadA(abase + nc * KC, DM, s, tid);
            loadB_nk(bbase + nc * KC, DM, s + B_OFF, tid);
            CP_COMMIT();
            CP_WAIT1();
        } else {
            asm volatile("cp.async.wait_group 0;" ::: "memory");
        }
        __syncthreads();
        compute_chunk<0>(smem, c & 1, wm, wn, lane, acc);
    }

    // epilogue: bias + relu + tf32 round -> g_feats
    const float* be = b_enc + (size_t)l * FT + n0;
#pragma unroll
    for (int mf = 0; mf < 4; mf++) {
        int r0 = m0 + wm * 64 + mf * 16 + (lane >> 2);
        float* d0 = g_feats + ((size_t)l * NPOS + r0) * FT + n0;
        float* d1 = d0 + 8 * FT;
#pragma unroll
        for (int nf = 0; nf < 8; nf++) {
            int c0 = wn * 64 + nf * 8 + (lane & 3) * 2;
            float b0 = be[c0], b1 = be[c0 + 1];
            uint2 v0 = { f2tf(fmaxf(acc[mf][nf][0] + b0, 0.f)),
                         f2tf(fmaxf(acc[mf][nf][1] + b1, 0.f)) };
            uint2 v1 = { f2tf(fmaxf(acc[mf][nf][2] + b0, 0.f)),
                         f2tf(fmaxf(acc[mf][nf][3] + b1, 0.f)) };
            *(uint2*)(d0 + c0) = v0;
            *(uint2*)(d1 + c0) = v1;
        }
    }
}

// ---------------------------------------------------------------------------
// Decoder partials: g_part[p] = feats[i] @ W_dec[i,j]. grid (DM/128, NPOS/256, NPAIR)
// ---------------------------------------------------------------------------
__global__ __launch_bounds__(NT, 1)
void decode_tc() {
    extern __shared__ float smem[];
    const int p = blockIdx.z, m0 = blockIdx.y * 256, n0 = blockIdx.x * 128;
    int j = 0, a0 = 0;
    while (a0 + j + 1 <= p) { a0 += j + 1; ++j; }
    const int i = p - a0;
    const int tid = threadIdx.x, lane = tid & 31, warp = tid >> 5;
    const int wm = warp & 3, wn = warp >> 2;
    const uint32_t sb = smem_u32(smem);

    float acc[4][8][4];
#pragma unroll
    for (int a = 0; a < 4; a++)
#pragma unroll
        for (int b = 0; b < 8; b++)
#pragma unroll
            for (int c = 0; c < 4; c++) acc[a][b][c] = 0.f;

    const float* abase = g_feats + ((size_t)i * NPOS + m0) * FT;
    const float* bbase = g_wdr + (size_t)p * FT * DM + n0;
    const int NC = FT / KC;     // 64

    loadA(abase, FT, sb, tid);
    loadB_kn(bbase, DM, sb + B_OFF, tid);
    CP_COMMIT();
    for (int c = 0; c < NC; c++) {
        int nc = c + 1;
        if (nc < NC) {
            uint32_t s = sb + (nc & 1) * STAGE;
            if (c > 0) { CP_WAIT1(); __syncthreads(); }
            loadA(abase + nc * KC, FT, s, tid);
            loadB_kn(bbase + (size_t)nc * KC * DM, DM, s + B_OFF, tid);
            CP_COMMIT();
            CP_WAIT1();
        } else {
            asm volatile("cp.async.wait_group 0;" ::: "memory");
        }
        __syncthreads();
        compute_chunk<1>(smem, c & 1, wm, wn, lane, acc);
    }

    // epilogue -> g_part
#pragma unroll
    for (int mf = 0; mf < 4; mf++) {
        int r0 = m0 + wm * 64 + mf * 16 + (lane >> 2);
        float* d0 = g_part + ((size_t)p * NPOS + r0) * DM + n0;
        float* d1 = d0 + 8 * DM;
#pragma unroll
        for (int nf = 0; nf < 8; nf++) {
            int c0 = wn * 64 + nf * 8 + (lane & 3) * 2;
            float2 v0 = { acc[mf][nf][0], acc[mf][nf][1] };
            float2 v1 = { acc[mf][nf][2], acc[mf][nf][3] };
            *(float2*)(d0 + c0) = v0;
            *(float2*)(d1 + c0) = v1;
        }
    }
}

// ---------------------------------------------------------------------------
// Fixed-order reduction over sources + bias. grid (NPOS*DM/1024, NL)
// ---------------------------------------------------------------------------
__global__ __launch_bounds__(256, 4)
void reduce_out(const float* __restrict__ b_dec, float* __restrict__ out) {
    const int jj = blockIdx.y;
    const int base = jj * (jj + 1) / 2;
    size_t lin = ((size_t)blockIdx.x * 256 + threadIdx.x) * 4;
    int d = (int)(lin % DM);
    float4 acc = *(const float4*)(b_dec + (size_t)jj * DM + d);
    for (int i = 0; i <= jj; i++) {
        float4 v = *(const float4*)(g_part + (size_t)(base + i) * NPOS * DM + lin);
        acc.x += v.x; acc.y += v.y; acc.z += v.z; acc.w += v.w;
    }
    *(float4*)(out + (size_t)jj * NPOS * DM + lin) = acc;
}

// ---------------------------------------------------------------------------
extern "C" void kernel_launch(void* const* d_in, const int* in_sizes, int n_in,
                              void* d_out, int out_size) {
    const float* x     = (const float*)d_in[0];
    const float* W_enc = (const float*)d_in[1];
    const float* b_enc = (const float*)d_in[2];
    const float* W_dec = (const float*)d_in[3];
    const float* b_dec = (const float*)d_in[4];
    float* out = (float*)d_out;

    static cudaStream_t s2 = nullptr;
    static cudaEvent_t evA = nullptr, evB = nullptr;
    if (!s2) {
        cudaFuncSetAttribute(encode_tc, cudaFuncAttributeMaxDynamicSharedMemorySize, SMEM_BYTES);
        cudaFuncSetAttribute(decode_tc, cudaFuncAttributeMaxDynamicSharedMemorySize, SMEM_BYTES);
        cudaStreamCreateWithFlags(&s2, cudaStreamNonBlocking);
        cudaEventCreateWithFlags(&evA, cudaEventDisableTiming);
        cudaEventCreateWithFlags(&evB, cudaEventDisableTiming);
    }

    float* g_xr_p;   cudaGetSymbolAddress((void**)&g_xr_p,  g_xr);
    float* g_wer_p;  cudaGetSymbolAddress((void**)&g_wer_p, g_wer);

    // Fork: W_dec rounding on side stream, overlapped with encode chain.
    cudaEventRecord(evA, 0);
    cudaStreamWaitEvent(s2, evA, 0);
    round_wdec<<<dim3((FT * DM) / 1024, NPAIR), 256, 0, s2>>>(W_dec);
    cudaEventRecord(evB, s2);

    round_copy<<<(NL * NPOS * DM) / 1024, 256>>>(x, g_xr_p);
    round_copy<<<(NL * FT * DM) / 1024, 256>>>(W_enc, g_wer_p);
    encode_tc<<<dim3(FT / 128, NPOS / 256, NL), NT, SMEM_BYTES>>>(b_enc);

    // Join, then decode + reduce.
    cudaStreamWaitEvent(0, evB, 0);
    decode_tc<<<dim3(DM / 128, NPOS / 256, NPAIR), NT, SMEM_BYTES>>>();
    reduce_out<<<dim3(NPOS * DM / 1024, NL), 256>>>(b_dec, out);
}

// round 9
// speedup vs baseline: 1.1537x; 1.0035x over previous
#include <cuda_runtime.h>
#include <cstdint>

#define NL    8
#define NPOS  1024
#define DM    768
#define FT    4096
#define NPAIR 36
#define NT    256           // 8 warps, 4x2 warp grid, 64x64 warp tiles

// ---------------------------------------------------------------------------
// Static device scratch
// ---------------------------------------------------------------------------
__device__ float g_xr  [(size_t)NL * NPOS * DM];        //  25 MB  rounded x
__device__ float g_wer [(size_t)NL * FT * DM];          // 100 MB  rounded W_enc
__device__ float g_wdr [(size_t)NPAIR * FT * DM];       // 453 MB  rounded triangular W_dec
__device__ float g_feats[(size_t)NL * NPOS * FT];       // 134 MB  feats (tf32-rounded)
__device__ float g_part[(size_t)NPAIR * NPOS * DM];     // 113 MB  decode partials

// ---------------------------------------------------------------------------
// Helpers
// ---------------------------------------------------------------------------
__device__ __forceinline__ unsigned f2tf(float x) {
    unsigned r;
    asm("cvt.rna.tf32.f32 %0, %1;" : "=r"(r) : "f"(x));
    return r;
}
__device__ __forceinline__ uint32_t smem_u32(const void* p) {
    uint32_t a;
    asm("{ .reg .u64 t; cvta.to.shared.u64 t, %1; cvt.u32.u64 %0, t; }" : "=r"(a) : "l"(p));
    return a;
}
#define CP_ASYNC16(dst, src) \
    asm volatile("cp.async.cg.shared.global [%0], [%1], 16;" :: "r"(dst), "l"(src))
#define CP_COMMIT() asm volatile("cp.async.commit_group;" ::: "memory")
#define CP_WAIT1()  asm volatile("cp.async.wait_group 1;" ::: "memory")

__device__ __forceinline__ void mma_tf32(float c[4],
                                         unsigned a0, unsigned a1, unsigned a2, unsigned a3,
                                         unsigned b0, unsigned b1) {
    asm volatile(
        "mma.sync.aligned.m16n8k8.row.col.f32.tf32.tf32.f32 "
        "{%0,%1,%2,%3}, {%4,%5,%6,%7}, {%8,%9}, {%0,%1,%2,%3};"
        : "+f"(c[0]), "+f"(c[1]), "+f"(c[2]), "+f"(c[3])
        : "r"(a0), "r"(a1), "r"(a2), "r"(a3), "r"(b0), "r"(b1));
}

// ---------------------------------------------------------------------------
// SMEM: 2 stages, K-chunk 64.
//   A tile 256x64 (stride 68 floats)  = 69632 B
//   encode B: 128x64 (stride 68)      = 34816 B
//   decode B: 64x128 (stride 136)     = 34816 B
// ---------------------------------------------------------------------------
#define STAGES 2
#define KC    64
#define ASTR  68
#define BKSTR 136
#define A_BYTES (256 * ASTR * 4)         // 69632
#define B_OFF   A_BYTES
#define B_BYTES (128 * ASTR * 4)         // 34816
#define STAGE   (A_BYTES + B_BYTES)      // 104448
#define SMEM_BYTES (STAGES * STAGE)      // 208896

// A loader: 256 rows x 64 floats (16 float4/row), K-contiguous source
__device__ __forceinline__ void loadA(const float* __restrict__ src, size_t gstr,
                                      uint32_t dst, int tid) {
#pragma unroll
    for (int q = 0; q < 16; q++) {
        int idx = tid + q * NT;
        int row = idx >> 4, seg = idx & 15;
        CP_ASYNC16(dst + (row * ASTR + seg * 4) * 4, src + (size_t)row * gstr + seg * 4);
    }
}
// decode B: 64 k-rows x 128 n-floats (32 float4/row), n-contiguous source
__device__ __forceinline__ void loadB_kn(const float* __restrict__ src, size_t gstr,
                                         uint32_t dst, int tid) {
#pragma unroll
    for (int q = 0; q < 8; q++) {
        int idx = tid + q * NT;
        int row = idx >> 5, seg = idx & 31;
        CP_ASYNC16(dst + (row * BKSTR + seg * 4) * 4, src + (size_t)row * gstr + seg * 4);
    }
}
// encode B: 128 n-rows x 64 k-floats (16 float4/row), K-contiguous source
__device__ __forceinline__ void loadB_nk(const float* __restrict__ src, size_t gstr,
                                         uint32_t dst, int tid) {
#pragma unroll
    for (int q = 0; q < 8; q++) {
        int idx = tid + q * NT;
        int row = idx >> 4, seg = idx & 15;
        CP_ASYNC16(dst + (row * ASTR + seg * 4) * 4, src + (size_t)row * gstr + seg * 4);
    }
}

// Load all fragments for one kk step into (a, b).
template <int B_KN>
__device__ __forceinline__ void load_frags(const unsigned* __restrict__ As,
                                           const unsigned* __restrict__ Bs,
                                           int kk, int wm, int wn, int lane,
                                           unsigned a[4][4], unsigned b[8][2]) {
    const int kb = kk * 8;
    const int kc = kb + (lane & 3);
#pragma unroll
    for (int mf = 0; mf < 4; mf++) {
        int r0 = wm * 64 + mf * 16 + (lane >> 2);
        a[mf][0] = As[r0 * ASTR + kc];
        a[mf][1] = As[(r0 + 8) * ASTR + kc];
        a[mf][2] = As[r0 * ASTR + kc + 4];
        a[mf][3] = As[(r0 + 8) * ASTR + kc + 4];
    }
#pragma unroll
    for (int nf = 0; nf < 8; nf++) {
        int n = wn * 64 + nf * 8 + (lane >> 2);
        if (B_KN) {
            b[nf][0] = Bs[kc * BKSTR + n];
            b[nf][1] = Bs[(kc + 4) * BKSTR + n];
        } else {
            b[nf][0] = Bs[n * ASTR + kc];
            b[nf][1] = Bs[n * ASTR + kc + 4];
        }
    }
}

// compute one K=64 chunk; warp tile 64(M) x 64(N); 4x2 warp grid.
// Register ping-pong: fragments for kk+1 load while kk's MMAs execute.
template <int B_KN>
__device__ __forceinline__ void compute_chunk(const float* __restrict__ smem, int stage,
                                              int wm, int wn, int lane,
                                              float acc[4][8][4]) {
    const unsigned* As = (const unsigned*)(smem) + stage * (STAGE / 4);
    const unsigned* Bs = As + A_BYTES / 4;

    unsigned a[2][4][4], b[2][8][2];
    load_frags<B_KN>(As, Bs, 0, wm, wn, lane, a[0], b[0]);
#pragma unroll
    for (int kk = 0; kk < 8; kk++) {
        const int cur = kk & 1;
        if (kk < 7)
            load_frags<B_KN>(As, Bs, kk + 1, wm, wn, lane, a[cur ^ 1], b[cur ^ 1]);
#pragma unroll
        for (int mf = 0; mf < 4; mf++)
#pragma unroll
            for (int nf = 0; nf < 8; nf++)
                mma_tf32(acc[mf][nf], a[cur][mf][0], a[cur][mf][1],
                         a[cur][mf][2], a[cur][mf][3],
                         b[cur][nf][0], b[cur][nf][1]);
    }
}

// ---------------------------------------------------------------------------
// Prep kernels
// ---------------------------------------------------------------------------
__global__ void round_copy(const float* __restrict__ src, float* __restrict__ dst) {
    size_t i = ((size_t)blockIdx.x * 256 + threadIdx.x) * 4;
    float4 v = *(const float4*)(src + i);
    uint4 o = { f2tf(v.x), f2tf(v.y), f2tf(v.z), f2tf(v.w) };
    *(uint4*)(dst + i) = o;
}
__global__ void round_wdec(const float* __restrict__ W_dec) {
    int p = blockIdx.y;
    int j = 0, a = 0;
    while (a + j + 1 <= p) { a += j + 1; ++j; }
    int i = p - a;
    const float* src = W_dec + (size_t)(i * NL + j) * FT * DM;
    float* dst = g_wdr + (size_t)p * FT * DM;
    size_t e = ((size_t)blockIdx.x * 256 + threadIdx.x) * 4;
    float4 v = *(const float4*)(src + e);
    uint4 o = { f2tf(v.x), f2tf(v.y), f2tf(v.z), f2tf(v.w) };
    *(uint4*)(dst + e) = o;
}

// ---------------------------------------------------------------------------
// Encoder: feats = relu(x @ W_enc^T + b_enc). grid (FT/128, NPOS/256, NL)
// ---------------------------------------------------------------------------
__global__ __launch_bounds__(NT, 1)
void encode_tc(const float* __restrict__ b_enc) {
    extern __shared__ float smem[];
    const int l = blockIdx.z, m0 = blockIdx.y * 256, n0 = blockIdx.x * 128;
    const int tid = threadIdx.x, lane = tid & 31, warp = tid >> 5;
    const int wm = warp & 3, wn = warp >> 2;
    const uint32_t sb = smem_u32(smem);

    float acc[4][8][4];
#pragma unroll
    for (int a = 0; a < 4; a++)
#pragma unroll
        for (int b = 0; b < 8; b++)
#pragma unroll
            for (int c = 0; c < 4; c++) acc[a][b][c] = 0.f;

    const float* abase = g_xr  + ((size_t)l * NPOS + m0) * DM;
    const float* bbase = g_wer + ((size_t)l * FT + n0) * DM;
    const int NC = DM / KC;     // 12

    loadA(abase, DM, sb, tid);
    loadB_nk(bbase, DM, sb + B_OFF, tid);
    CP_COMMIT();
    for (int c = 0; c < NC; c++) {
        int nc = c + 1;
        if (nc < NC) {
            uint32_t s = sb + (nc & 1) * STAGE;
            if (c > 0) { CP_WAIT1(); __syncthreads(); }
            loadA(abase + nc * KC, DM, s, tid);
            loadB_nk(bbase + nc * KC, DM, s + B_OFF, tid);
            CP_COMMIT();
            CP_WAIT1();
        } else {
            asm volatile("cp.async.wait_group 0;" ::: "memory");
        }
        __syncthreads();
        compute_chunk<0>(smem, c & 1, wm, wn, lane, acc);
    }

    // epilogue: bias + relu + tf32 round -> g_feats
    const float* be = b_enc + (size_t)l * FT + n0;
#pragma unroll
    for (int mf = 0; mf < 4; mf++) {
        int r0 = m0 + wm * 64 + mf * 16 + (lane >> 2);
        float* d0 = g_feats + ((size_t)l * NPOS + r0) * FT + n0;
        float* d1 = d0 + 8 * FT;
#pragma unroll
        for (int nf = 0; nf < 8; nf++) {
            int c0 = wn * 64 + nf * 8 + (lane & 3) * 2;
            float b0 = be[c0], b1 = be[c0 + 1];
            uint2 v0 = { f2tf(fmaxf(acc[mf][nf][0] + b0, 0.f)),
                         f2tf(fmaxf(acc[mf][nf][1] + b1, 0.f)) };
            uint2 v1 = { f2tf(fmaxf(acc[mf][nf][2] + b0, 0.f)),
                         f2tf(fmaxf(acc[mf][nf][3] + b1, 0.f)) };
            *(uint2*)(d0 + c0) = v0;
            *(uint2*)(d1 + c0) = v1;
        }
    }
}

// ---------------------------------------------------------------------------
// Decoder partials: g_part[p] = feats[i] @ W_dec[i,j]. grid (DM/128, NPOS/256, NPAIR)
// ---------------------------------------------------------------------------
__global__ __launch_bounds__(NT, 1)
void decode_tc() {
    extern __shared__ float smem[];
    const int p = blockIdx.z, m0 = blockIdx.y * 256, n0 = blockIdx.x * 128;
    int j = 0, a0 = 0;
    while (a0 + j + 1 <= p) { a0 += j + 1; ++j; }
    const int i = p - a0;
    const int tid = threadIdx.x, lane = tid & 31, warp = tid >> 5;
    const int wm = warp & 3, wn = warp >> 2;
    const uint32_t sb = smem_u32(smem);

    float acc[4][8][4];
#pragma unroll
    for (int a = 0; a < 4; a++)
#pragma unroll
        for (int b = 0; b < 8; b++)
#pragma unroll
            for (int c = 0; c < 4; c++) acc[a][b][c] = 0.f;

    const float* abase = g_feats + ((size_t)i * NPOS + m0) * FT;
    const float* bbase = g_wdr + (size_t)p * FT * DM + n0;
    const int NC = FT / KC;     // 64

    loadA(abase, FT, sb, tid);
    loadB_kn(bbase, DM, sb + B_OFF, tid);
    CP_COMMIT();
    for (int c = 0; c < NC; c++) {
        int nc = c + 1;
        if (nc < NC) {
            uint32_t s = sb + (nc & 1) * STAGE;
            if (c > 0) { CP_WAIT1(); __syncthreads(); }
            loadA(abase + nc * KC, FT, s, tid);
            loadB_kn(bbase + (size_t)nc * KC * DM, DM, s + B_OFF, tid);
            CP_COMMIT();
            CP_WAIT1();
        } else {
            asm volatile("cp.async.wait_group 0;" ::: "memory");
        }
        __syncthreads();
        compute_chunk<1>(smem, c & 1, wm, wn, lane, acc);
    }

    // epilogue -> g_part
#pragma unroll
    for (int mf = 0; mf < 4; mf++) {
        int r0 = m0 + wm * 64 + mf * 16 + (lane >> 2);
        float* d0 = g_part + ((size_t)p * NPOS + r0) * DM + n0;
        float* d1 = d0 + 8 * DM;
#pragma unroll
        for (int nf = 0; nf < 8; nf++) {
            int c0 = wn * 64 + nf * 8 + (lane & 3) * 2;
            float2 v0 = { acc[mf][nf][0], acc[mf][nf][1] };
            float2 v1 = { acc[mf][nf][2], acc[mf][nf][3] };
            *(float2*)(d0 + c0) = v0;
            *(float2*)(d1 + c0) = v1;
        }
    }
}

// ---------------------------------------------------------------------------
// Fixed-order reduction over sources + bias. grid (NPOS*DM/1024, NL)
// ---------------------------------------------------------------------------
__global__ __launch_bounds__(256, 4)
void reduce_out(const float* __restrict__ b_dec, float* __restrict__ out) {
    const int jj = blockIdx.y;
    const int base = jj * (jj + 1) / 2;
    size_t lin = ((size_t)blockIdx.x * 256 + threadIdx.x) * 4;
    int d = (int)(lin % DM);
    float4 acc = *(const float4*)(b_dec + (size_t)jj * DM + d);
    for (int i = 0; i <= jj; i++) {
        float4 v = *(const float4*)(g_part + (size_t)(base + i) * NPOS * DM + lin);
        acc.x += v.x; acc.y += v.y; acc.z += v.z; acc.w += v.w;
    }
    *(float4*)(out + (size_t)jj * NPOS * DM + lin) = acc;
}

// ---------------------------------------------------------------------------
extern "C" void kernel_launch(void* const* d_in, const int* in_sizes, int n_in,
                              void* d_out, int out_size) {
    const float* x     = (const float*)d_in[0];
    const float* W_enc = (const float*)d_in[1];
    const float* b_enc = (const float*)d_in[2];
    const float* W_dec = (const float*)d_in[3];
    const float* b_dec = (const float*)d_in[4];
    float* out = (float*)d_out;

    static cudaStream_t s2 = nullptr;
    static cudaEvent_t evA = nullptr, evB = nullptr;
    if (!s2) {
        cudaFuncSetAttribute(encode_tc, cudaFuncAttributeMaxDynamicSharedMemorySize, SMEM_BYTES);
        cudaFuncSetAttribute(decode_tc, cudaFuncAttributeMaxDynamicSharedMemorySize, SMEM_BYTES);
        cudaStreamCreateWithFlags(&s2, cudaStreamNonBlocking);
        cudaEventCreateWithFlags(&evA, cudaEventDisableTiming);
        cudaEventCreateWithFlags(&evB, cudaEventDisableTiming);
    }

    float* g_xr_p;   cudaGetSymbolAddress((void**)&g_xr_p,  g_xr);
    float* g_wer_p;  cudaGetSymbolAddress((void**)&g_wer_p, g_wer);

    // Fork: W_dec rounding on side stream, overlapped with encode chain.
    cudaEventRecord(evA, 0);
    cudaStreamWaitEvent(s2, evA, 0);
    round_wdec<<<dim3((FT * DM) / 1024, NPAIR), 256, 0, s2>>>(W_dec);
    cudaEventRecord(evB, s2);

    round_copy<<<(NL * NPOS * DM) / 1024, 256>>>(x, g_xr_p);
    round_copy<<<(NL * FT * DM) / 1024, 256>>>(W_enc, g_wer_p);
    encode_tc<<<dim3(FT / 128, NPOS / 256, NL), NT, SMEM_BYTES>>>(b_enc);

    // Join, then decode + reduce.
    cudaStreamWaitEvent(0, evB, 0);
    decode_tc<<<dim3(DM / 128, NPOS / 256, NPAIR), NT, SMEM_BYTES>>>();
    reduce_out<<<dim3(NPOS * DM / 1024, NL), 256>>>(b_dec, out);
}

// round 10
// speedup vs baseline: 1.9441x; 1.6852x over previous
#include <cuda_runtime.h>
#include <cuda_fp16.h>
#include <cstdint>

#define NL    8
#define NPOS  1024
#define DM    768
#define FT    4096
#define NPAIR 36
#define NT    256           // 8 warps, 4x2 warp grid, 64x64 warp tiles

// ---------------------------------------------------------------------------
// Static device scratch (half precision planes)
// ---------------------------------------------------------------------------
__device__ __half g_xr  [(size_t)NL * NPOS * DM];       // 12.5 MB
__device__ __half g_wer [(size_t)NL * FT * DM];         //  50 MB
__device__ __half g_wdT [(size_t)NPAIR * DM * FT];      // 226 MB  [p][d][f]
__device__ __half g_feats[(size_t)NL * NPOS * FT];      //  67 MB
__device__ float  g_part[(size_t)NPAIR * NPOS * DM];    // 113 MB  fp32 partials

// ---------------------------------------------------------------------------
// Helpers
// ---------------------------------------------------------------------------
__device__ __forceinline__ uint32_t smem_u32(const void* p) {
    uint32_t a;
    asm("{ .reg .u64 t; cvta.to.shared.u64 t, %1; cvt.u32.u64 %0, t; }" : "=r"(a) : "l"(p));
    return a;
}
#define CP_ASYNC16(dst, src) \
    asm volatile("cp.async.cg.shared.global [%0], [%1], 16;" :: "r"(dst), "l"(src))
#define CP_COMMIT() asm volatile("cp.async.commit_group;" ::: "memory")
#define CP_WAIT1()  asm volatile("cp.async.wait_group 1;" ::: "memory")

__device__ __forceinline__ void mma_f16(float c[4],
                                        unsigned a0, unsigned a1, unsigned a2, unsigned a3,
                                        unsigned b0, unsigned b1) {
    asm volatile(
        "mma.sync.aligned.m16n8k16.row.col.f32.f16.f16.f32 "
        "{%0,%1,%2,%3}, {%4,%5,%6,%7}, {%8,%9}, {%0,%1,%2,%3};"
        : "+f"(c[0]), "+f"(c[1]), "+f"(c[2]), "+f"(c[3])
        : "r"(a0), "r"(a1), "r"(a2), "r"(a3), "r"(b0), "r"(b1));
}

// ---------------------------------------------------------------------------
// SMEM: 2 stages, K-chunk 64 (halves).
//   A tile 256 x 64 halves, row stride 72 halves (144 B)   = 36864 B
//   B tile 128 x 64 halves, row stride 72 halves           = 18432 B
// Both tiles [row][k] with k contiguous (B pre-transposed for decode).
// ---------------------------------------------------------------------------
#define STAGES 2
#define KC    64
#define HSTR  72                          // halves per row (36 words)
#define A_BYTES (256 * HSTR * 2)          // 36864
#define B_OFF   A_BYTES
#define B_BYTES (128 * HSTR * 2)          // 18432
#define STAGE   (A_BYTES + B_BYTES)       // 55296
#define SMEM_BYTES (STAGES * STAGE)       // 110592

// A loader: 256 rows x 64 halves (8 x 16B per row); gstr in halves
__device__ __forceinline__ void loadA(const __half* __restrict__ src, size_t gstr,
                                      uint32_t dst, int tid) {
#pragma unroll
    for (int q = 0; q < 8; q++) {
        int idx = tid + q * NT;
        int row = idx >> 3, seg = idx & 7;
        CP_ASYNC16(dst + row * (HSTR * 2) + seg * 16, src + (size_t)row * gstr + seg * 8);
    }
}
// B loader: 128 rows x 64 halves
__device__ __forceinline__ void loadB(const __half* __restrict__ src, size_t gstr,
                                      uint32_t dst, int tid) {
#pragma unroll
    for (int q = 0; q < 4; q++) {
        int idx = tid + q * NT;
        int row = idx >> 3, seg = idx & 7;
        CP_ASYNC16(dst + row * (HSTR * 2) + seg * 16, src + (size_t)row * gstr + seg * 8);
    }
}

// compute one K=64 chunk = 4 kk-steps of K=16; warp tile 64(M) x 64(N)
__device__ __forceinline__ void compute_chunk(const float* __restrict__ smem, int stage,
                                              int wm, int wn, int lane,
                                              float acc[4][8][4]) {
    const unsigned* As = (const unsigned*)(smem) + stage * (STAGE / 4);
    const unsigned* Bs = As + A_BYTES / 4;
    const int lq = lane & 3, lr = lane >> 2;
#pragma unroll
    for (int kk = 0; kk < 4; kk++) {
        const int kb = kk * 8;            // 16 halves = 8 words per kk
        unsigned a[4][4], b[8][2];
#pragma unroll
        for (int mf = 0; mf < 4; mf++) {
            int r0 = wm * 64 + mf * 16 + lr;
            a[mf][0] = As[r0 * 36 + kb + lq];
            a[mf][1] = As[(r0 + 8) * 36 + kb + lq];
            a[mf][2] = As[r0 * 36 + kb + lq + 4];
            a[mf][3] = As[(r0 + 8) * 36 + kb + lq + 4];
        }
#pragma unroll
        for (int nf = 0; nf < 8; nf++) {
            int n = wn * 64 + nf * 8 + lr;
            b[nf][0] = Bs[n * 36 + kb + lq];
            b[nf][1] = Bs[n * 36 + kb + lq + 4];
        }
#pragma unroll
        for (int mf = 0; mf < 4; mf++)
#pragma unroll
            for (int nf = 0; nf < 8; nf++)
                mma_f16(acc[mf][nf], a[mf][0], a[mf][1], a[mf][2], a[mf][3],
                        b[nf][0], b[nf][1]);
    }
}

// ---------------------------------------------------------------------------
// Prep kernels
// ---------------------------------------------------------------------------
// fp32 -> half copy, 8 elements per thread
__global__ void half_copy(const float* __restrict__ src, __half* __restrict__ dst) {
    size_t i = ((size_t)blockIdx.x * 256 + threadIdx.x) * 8;
    float4 v0 = *(const float4*)(src + i);
    float4 v1 = *(const float4*)(src + i + 4);
    __half2 h[4] = { __floats2half2_rn(v0.x, v0.y), __floats2half2_rn(v0.z, v0.w),
                     __floats2half2_rn(v1.x, v1.y), __floats2half2_rn(v1.z, v1.w) };
    *(uint4*)(dst + i) = *(uint4*)h;
}
// W_dec[i,j][f][d] -> g_wdT[p][d][f], half
__global__ void wdec_T(const float* __restrict__ W_dec) {
    int p = blockIdx.z;
    int j = 0, a = 0;
    while (a + j + 1 <= p) { a += j + 1; ++j; }
    int i = p - a;
    int f0 = blockIdx.x * 32, d0 = blockIdx.y * 32;
    int tx = threadIdx.x, ty = threadIdx.y;
    __shared__ float t[32][33];
    const float* src = W_dec + (size_t)(i * NL + j) * FT * DM;
#pragma unroll
    for (int r = 0; r < 4; r++)
        t[ty + r * 8][tx] = src[(size_t)(f0 + ty + r * 8) * DM + d0 + tx];
    __syncthreads();
    __half* dst = g_wdT + (size_t)p * DM * FT;
#pragma unroll
    for (int r = 0; r < 4; r++)
        dst[(size_t)(d0 + ty + r * 8) * FT + f0 + tx] = __float2half_rn(t[tx][ty + r * 8]);
}

// ---------------------------------------------------------------------------
// Encoder: feats = relu(x @ W_enc^T + b_enc) -> half. grid (FT/128, NPOS/256, NL)
// ---------------------------------------------------------------------------
__global__ __launch_bounds__(NT, 1)
void encode_tc(const float* __restrict__ b_enc) {
    extern __shared__ float smem[];
    const int l = blockIdx.z, m0 = blockIdx.y * 256, n0 = blockIdx.x * 128;
    const int tid = threadIdx.x, lane = tid & 31, warp = tid >> 5;
    const int wm = warp & 3, wn = warp >> 2;
    const uint32_t sb = smem_u32(smem);

    float acc[4][8][4];
#pragma unroll
    for (int a = 0; a < 4; a++)
#pragma unroll
        for (int b = 0; b < 8; b++)
#pragma unroll
            for (int c = 0; c < 4; c++) acc[a][b][c] = 0.f;

    const __half* abase = g_xr  + ((size_t)l * NPOS + m0) * DM;
    const __half* bbase = g_wer + ((size_t)l * FT + n0) * DM;
    const int NC = DM / KC;     // 12

    loadA(abase, DM, sb, tid);
    loadB(bbase, DM, sb + B_OFF, tid);
    CP_COMMIT();
    for (int c = 0; c < NC; c++) {
        int nc = c + 1;
        if (nc < NC) {
            uint32_t s = sb + (nc & 1) * STAGE;
            if (c > 0) { CP_WAIT1(); __syncthreads(); }
            loadA(abase + nc * KC, DM, s, tid);
            loadB(bbase + nc * KC, DM, s + B_OFF, tid);
            CP_COMMIT();
            CP_WAIT1();
        } else {
            asm volatile("cp.async.wait_group 0;" ::: "memory");
        }
        __syncthreads();
        compute_chunk(smem, c & 1, wm, wn, lane, acc);
    }

    // epilogue: bias + relu -> half g_feats
    const float* be = b_enc + (size_t)l * FT + n0;
#pragma unroll
    for (int mf = 0; mf < 4; mf++) {
        int r0 = m0 + wm * 64 + mf * 16 + (lane >> 2);
        __half* d0 = g_feats + ((size_t)l * NPOS + r0) * FT + n0;
        __half* d1 = d0 + 8 * FT;
#pragma unroll
        for (int nf = 0; nf < 8; nf++) {
            int c0 = wn * 64 + nf * 8 + (lane & 3) * 2;
            float b0 = be[c0], b1 = be[c0 + 1];
            __half2 v0 = __floats2half2_rn(fmaxf(acc[mf][nf][0] + b0, 0.f),
                                           fmaxf(acc[mf][nf][1] + b1, 0.f));
            __half2 v1 = __floats2half2_rn(fmaxf(acc[mf][nf][2] + b0, 0.f),
                                           fmaxf(acc[mf][nf][3] + b1, 0.f));
            *(__half2*)(d0 + c0) = v0;
            *(__half2*)(d1 + c0) = v1;
        }
    }
}

// ---------------------------------------------------------------------------
// Decoder partials: g_part[p] = feats[i] @ W_dec[i,j]. grid (DM/128, NPOS/256, NPAIR)
// ---------------------------------------------------------------------------
__global__ __launch_bounds__(NT, 1)
void decode_tc() {
    extern __shared__ float smem[];
    const int p = blockIdx.z, m0 = blockIdx.y * 256, n0 = blockIdx.x * 128;
    int j = 0, a0 = 0;
    while (a0 + j + 1 <= p) { a0 += j + 1; ++j; }
    const int i = p - a0;
    const int tid = threadIdx.x, lane = tid & 31, warp = tid >> 5;
    const int wm = warp & 3, wn = warp >> 2;
    const uint32_t sb = smem_u32(smem);

    float acc[4][8][4];
#pragma unroll
    for (int a = 0; a < 4; a++)
#pragma unroll
        for (int b = 0; b < 8; b++)
#pragma unroll
            for (int c = 0; c < 4; c++) acc[a][b][c] = 0.f;

    const __half* abase = g_feats + ((size_t)i * NPOS + m0) * FT;
    const __half* bbase = g_wdT + (size_t)p * DM * FT + (size_t)n0 * FT;
    const int NC = FT / KC;     // 64

    loadA(abase, FT, sb, tid);
    loadB(bbase, FT, sb + B_OFF, tid);
    CP_COMMIT();
    for (int c = 0; c < NC; c++) {
        int nc = c + 1;
        if (nc < NC) {
            uint32_t s = sb + (nc & 1) * STAGE;
            if (c > 0) { CP_WAIT1(); __syncthreads(); }
            loadA(abase + nc * KC, FT, s, tid);
            loadB(bbase + nc * KC, FT, s + B_OFF, tid);
            CP_COMMIT();
            CP_WAIT1();
        } else {
            asm volatile("cp.async.wait_group 0;" ::: "memory");
        }
        __syncthreads();
        compute_chunk(smem, c & 1, wm, wn, lane, acc);
    }

    // epilogue -> fp32 g_part
#pragma unroll
    for (int mf = 0; mf < 4; mf++) {
        int r0 = m0 + wm * 64 + mf * 16 + (lane >> 2);
        float* d0 = g_part + ((size_t)p * NPOS + r0) * DM + n0;
        float* d1 = d0 + 8 * DM;
#pragma unroll
        for (int nf = 0; nf < 8; nf++) {
            int c0 = wn * 64 + nf * 8 + (lane & 3) * 2;
            float2 v0 = { acc[mf][nf][0], acc[mf][nf][1] };
            float2 v1 = { acc[mf][nf][2], acc[mf][nf][3] };
            *(float2*)(d0 + c0) = v0;
            *(float2*)(d1 + c0) = v1;
        }
    }
}

// ---------------------------------------------------------------------------
// Fixed-order reduction over sources + bias. grid (NPOS*DM/1024, NL)
// ---------------------------------------------------------------------------
__global__ __launch_bounds__(256, 4)
void reduce_out(const float* __restrict__ b_dec, float* __restrict__ out) {
    const int jj = blockIdx.y;
    const int base = jj * (jj + 1) / 2;
    size_t lin = ((size_t)blockIdx.x * 256 + threadIdx.x) * 4;
    int d = (int)(lin % DM);
    float4 acc = *(const float4*)(b_dec + (size_t)jj * DM + d);
    for (int i = 0; i <= jj; i++) {
        float4 v = *(const float4*)(g_part + (size_t)(base + i) * NPOS * DM + lin);
        acc.x += v.x; acc.y += v.y; acc.z += v.z; acc.w += v.w;
    }
    *(float4*)(out + (size_t)jj * NPOS * DM + lin) = acc;
}

// ---------------------------------------------------------------------------
extern "C" void kernel_launch(void* const* d_in, const int* in_sizes, int n_in,
                              void* d_out, int out_size) {
    const float* x     = (const float*)d_in[0];
    const float* W_enc = (const float*)d_in[1];
    const float* b_enc = (const float*)d_in[2];
    const float* W_dec = (const float*)d_in[3];
    const float* b_dec = (const float*)d_in[4];
    float* out = (float*)d_out;

    static cudaStream_t s2 = nullptr;
    static cudaEvent_t evA = nullptr, evB = nullptr;
    if (!s2) {
        cudaFuncSetAttribute(encode_tc, cudaFuncAttributeMaxDynamicSharedMemorySize, SMEM_BYTES);
        cudaFuncSetAttribute(decode_tc, cudaFuncAttributeMaxDynamicSharedMemorySize, SMEM_BYTES);
        cudaStreamCreateWithFlags(&s2, cudaStreamNonBlocking);
        cudaEventCreateWithFlags(&evA, cudaEventDisableTiming);
        cudaEventCreateWithFlags(&evB, cudaEventDisableTiming);
    }

    __half* g_xr_p;   cudaGetSymbolAddress((void**)&g_xr_p,  g_xr);
    __half* g_wer_p;  cudaGetSymbolAddress((void**)&g_wer_p, g_wer);

    // Fork: W_dec transpose+convert on side stream, overlapped with encode chain.
    cudaEventRecord(evA, 0);
    cudaStreamWaitEvent(s2, evA, 0);
    wdec_T<<<dim3(FT / 32, DM / 32, NPAIR), dim3(32, 8), 0, s2>>>(W_dec);
    cudaEventRecord(evB, s2);

    half_copy<<<(NL * NPOS * DM) / 2048, 256>>>(x, g_xr_p);
    half_copy<<<(NL * FT * DM) / 2048, 256>>>(W_enc, g_wer_p);
    encode_tc<<<dim3(FT / 128, NPOS / 256, NL), NT, SMEM_BYTES>>>(b_enc);

    // Join, then decode + reduce.
    cudaStreamWaitEvent(0, evB, 0);
    decode_tc<<<dim3(DM / 128, NPOS / 256, NPAIR), NT, SMEM_BYTES>>>();
    reduce_out<<<dim3(NPOS * DM / 1024, NL), 256>>>(b_dec, out);
}

// round 11
// speedup vs baseline: 2.0237x; 1.0410x over previous
#include <cuda_runtime.h>
#include <cuda_fp16.h>
#include <cstdint>

#define NL    8
#define NPOS  1024
#define DM    768
#define FT    4096
#define NPAIR 36
#define NT    256           // 8 warps: 2(M) x 4(N) grid of 64x32 warp tiles

// ---------------------------------------------------------------------------
// Static device scratch (half precision planes)
// ---------------------------------------------------------------------------
__device__ __half g_xr  [(size_t)NL * NPOS * DM];       // 12.5 MB
__device__ __half g_wer [(size_t)NL * FT * DM];         //  50 MB
__device__ __half g_wdT [(size_t)NPAIR * DM * FT];      // 226 MB  [p][d][f]
__device__ __half g_feats[(size_t)NL * NPOS * FT];      //  67 MB
__device__ float  g_part[(size_t)NPAIR * NPOS * DM];    // 113 MB  fp32 partials

// ---------------------------------------------------------------------------
// Helpers
// ---------------------------------------------------------------------------
__device__ __forceinline__ uint32_t smem_u32(const void* p) {
    uint32_t a;
    asm("{ .reg .u64 t; cvta.to.shared.u64 t, %1; cvt.u32.u64 %0, t; }" : "=r"(a) : "l"(p));
    return a;
}
#define CP_ASYNC16(dst, src) \
    asm volatile("cp.async.cg.shared.global [%0], [%1], 16;" :: "r"(dst), "l"(src))
#define CP_COMMIT() asm volatile("cp.async.commit_group;" ::: "memory")
#define CP_WAIT1()  asm volatile("cp.async.wait_group 1;" ::: "memory")

__device__ __forceinline__ void mma_f16(float c[4],
                                        unsigned a0, unsigned a1, unsigned a2, unsigned a3,
                                        unsigned b0, unsigned b1) {
    asm volatile(
        "mma.sync.aligned.m16n8k16.row.col.f32.f16.f16.f32 "
        "{%0,%1,%2,%3}, {%4,%5,%6,%7}, {%8,%9}, {%0,%1,%2,%3};"
        : "+f"(c[0]), "+f"(c[1]), "+f"(c[2]), "+f"(c[3])
        : "r"(a0), "r"(a1), "r"(a2), "r"(a3), "r"(b0), "r"(b1));
}

// ---------------------------------------------------------------------------
// SMEM: 2 stages, K-chunk 64 halves.
//   A tile 128 x 64 halves, row stride 72 halves (144 B)   = 18432 B
//   B tile 128 x 64 halves, row stride 72 halves           = 18432 B
// Both [row][k], k contiguous (W_dec pre-transposed).
// ---------------------------------------------------------------------------
#define STAGES 2
#define KC    64
#define HSTR  72
#define A_BYTES (128 * HSTR * 2)          // 18432
#define B_OFF   A_BYTES
#define B_BYTES (128 * HSTR * 2)          // 18432
#define STAGE   (A_BYTES + B_BYTES)       // 36864
#define SMEM_BYTES (STAGES * STAGE)       // 73728 per CTA (x2 CTAs = 147456)

// tile loader: 128 rows x 64 halves (8 x 16B per row); gstr in halves
__device__ __forceinline__ void load_tile(const __half* __restrict__ src, size_t gstr,
                                          uint32_t dst, int tid) {
#pragma unroll
    for (int q = 0; q < 4; q++) {
        int idx = tid + q * NT;
        int row = idx >> 3, seg = idx & 7;
        CP_ASYNC16(dst + row * (HSTR * 2) + seg * 16, src + (size_t)row * gstr + seg * 8);
    }
}

// compute one K=64 chunk = 4 kk-steps of K=16; warp tile 64(M) x 32(N)
__device__ __forceinline__ void compute_chunk(const float* __restrict__ smem, int stage,
                                              int wm, int wn, int lane,
                                              float acc[4][4][4]) {
    const unsigned* As = (const unsigned*)(smem) + stage * (STAGE / 4);
    const unsigned* Bs = As + A_BYTES / 4;
    const int lq = lane & 3, lr = lane >> 2;
#pragma unroll
    for (int kk = 0; kk < 4; kk++) {
        const int kb = kk * 8;            // 16 halves = 8 words per kk
        unsigned a[4][4], b[4][2];
#pragma unroll
        for (int mf = 0; mf < 4; mf++) {
            int r0 = wm * 64 + mf * 16 + lr;
            a[mf][0] = As[r0 * 36 + kb + lq];
            a[mf][1] = As[(r0 + 8) * 36 + kb + lq];
            a[mf][2] = As[r0 * 36 + kb + lq + 4];
            a[mf][3] = As[(r0 + 8) * 36 + kb + lq + 4];
        }
#pragma unroll
        for (int nf = 0; nf < 4; nf++) {
            int n = wn * 32 + nf * 8 + lr;
            b[nf][0] = Bs[n * 36 + kb + lq];
            b[nf][1] = Bs[n * 36 + kb + lq + 4];
        }
#pragma unroll
        for (int mf = 0; mf < 4; mf++)
#pragma unroll
            for (int nf = 0; nf < 4; nf++)
                mma_f16(acc[mf][nf], a[mf][0], a[mf][1], a[mf][2], a[mf][3],
                        b[nf][0], b[nf][1]);
    }
}

// ---------------------------------------------------------------------------
// Prep kernels
// ---------------------------------------------------------------------------
__global__ void half_copy(const float* __restrict__ src, __half* __restrict__ dst) {
    size_t i = ((size_t)blockIdx.x * 256 + threadIdx.x) * 8;
    float4 v0 = *(const float4*)(src + i);
    float4 v1 = *(const float4*)(src + i + 4);
    __half2 h[4] = { __floats2half2_rn(v0.x, v0.y), __floats2half2_rn(v0.z, v0.w),
                     __floats2half2_rn(v1.x, v1.y), __floats2half2_rn(v1.z, v1.w) };
    *(uint4*)(dst + i) = *(uint4*)h;
}
// W_dec[i,j][f][d] -> g_wdT[p][d][f], half
__global__ void wdec_T(const float* __restrict__ W_dec) {
    int p = blockIdx.z;
    int j = 0, a = 0;
    while (a + j + 1 <= p) { a += j + 1; ++j; }
    int i = p - a;
    int f0 = blockIdx.x * 32, d0 = blockIdx.y * 32;
    int tx = threadIdx.x, ty = threadIdx.y;
    __shared__ float t[32][33];
    const float* src = W_dec + (size_t)(i * NL + j) * FT * DM;
#pragma unroll
    for (int r = 0; r < 4; r++)
        t[ty + r * 8][tx] = src[(size_t)(f0 + ty + r * 8) * DM + d0 + tx];
    __syncthreads();
    __half* dst = g_wdT + (size_t)p * DM * FT;
#pragma unroll
    for (int r = 0; r < 4; r++)
        dst[(size_t)(d0 + ty + r * 8) * FT + f0 + tx] = __float2half_rn(t[tx][ty + r * 8]);
}

// ---------------------------------------------------------------------------
// Encoder: feats = relu(x @ W_enc^T + b_enc) -> half. grid (FT/128, NPOS/128, NL)
// ---------------------------------------------------------------------------
__global__ __launch_bounds__(NT, 2)
void encode_tc(const float* __restrict__ b_enc) {
    extern __shared__ float smem[];
    const int l = blockIdx.z, m0 = blockIdx.y * 128, n0 = blockIdx.x * 128;
    const int tid = threadIdx.x, lane = tid & 31, warp = tid >> 5;
    const int wm = warp & 1, wn = warp >> 1;   // 2 x 4 warp grid
    const uint32_t sb = smem_u32(smem);

    float acc[4][4][4];
#pragma unroll
    for (int a = 0; a < 4; a++)
#pragma unroll
        for (int b = 0; b < 4; b++)
#pragma unroll
            for (int c = 0; c < 4; c++) acc[a][b][c] = 0.f;

    const __half* abase = g_xr  + ((size_t)l * NPOS + m0) * DM;
    const __half* bbase = g_wer + ((size_t)l * FT + n0) * DM;
    const int NC = DM / KC;     // 12

    load_tile(abase, DM, sb, tid);
    load_tile(bbase, DM, sb + B_OFF, tid);
    CP_COMMIT();
    for (int c = 0; c < NC; c++) {
        int nc = c + 1;
        if (nc < NC) {
            uint32_t s = sb + (nc & 1) * STAGE;
            if (c > 0) { CP_WAIT1(); __syncthreads(); }
            load_tile(abase + nc * KC, DM, s, tid);
            load_tile(bbase + nc * KC, DM, s + B_OFF, tid);
            CP_COMMIT();
            CP_WAIT1();
        } else {
            asm volatile("cp.async.wait_group 0;" ::: "memory");
        }
        __syncthreads();
        compute_chunk(smem, c & 1, wm, wn, lane, acc);
    }

    // epilogue: bias + relu -> half g_feats
    const float* be = b_enc + (size_t)l * FT + n0;
#pragma unroll
    for (int mf = 0; mf < 4; mf++) {
        int r0 = m0 + wm * 64 + mf * 16 + (lane >> 2);
        __half* d0 = g_feats + ((size_t)l * NPOS + r0) * FT + n0;
        __half* d1 = d0 + 8 * FT;
#pragma unroll
        for (int nf = 0; nf < 4; nf++) {
            int c0 = wn * 32 + nf * 8 + (lane & 3) * 2;
            float b0 = be[c0], b1 = be[c0 + 1];
            __half2 v0 = __floats2half2_rn(fmaxf(acc[mf][nf][0] + b0, 0.f),
                                           fmaxf(acc[mf][nf][1] + b1, 0.f));
            __half2 v1 = __floats2half2_rn(fmaxf(acc[mf][nf][2] + b0, 0.f),
                                           fmaxf(acc[mf][nf][3] + b1, 0.f));
            *(__half2*)(d0 + c0) = v0;
            *(__half2*)(d1 + c0) = v1;
        }
    }
}

// ---------------------------------------------------------------------------
// Decoder partials: g_part[p] = feats[i] @ W_dec[i,j]. grid (DM/128, NPOS/128, NPAIR)
// ---------------------------------------------------------------------------
__global__ __launch_bounds__(NT, 2)
void decode_tc() {
    extern __shared__ float smem[];
    const int p = blockIdx.z, m0 = blockIdx.y * 128, n0 = blockIdx.x * 128;
    int j = 0, a0 = 0;
    while (a0 + j + 1 <= p) { a0 += j + 1; ++j; }
    const int i = p - a0;
    const int tid = threadIdx.x, lane = tid & 31, warp = tid >> 5;
    const int wm = warp & 1, wn = warp >> 1;
    const uint32_t sb = smem_u32(smem);

    float acc[4][4][4];
#pragma unroll
    for (int a = 0; a < 4; a++)
#pragma unroll
        for (int b = 0; b < 4; b++)
#pragma unroll
            for (int c = 0; c < 4; c++) acc[a][b][c] = 0.f;

    const __half* abase = g_feats + ((size_t)i * NPOS + m0) * FT;
    const __half* bbase = g_wdT + (size_t)p * DM * FT + (size_t)n0 * FT;
    const int NC = FT / KC;     // 64

    load_tile(abase, FT, sb, tid);
    load_tile(bbase, FT, sb + B_OFF, tid);
    CP_COMMIT();
    for (int c = 0; c < NC; c++) {
        int nc = c + 1;
        if (nc < NC) {
            uint32_t s = sb + (nc & 1) * STAGE;
            if (c > 0) { CP_WAIT1(); __syncthreads(); }
            load_tile(abase + nc * KC, FT, s, tid);
            load_tile(bbase + nc * KC, FT, s + B_OFF, tid);
            CP_COMMIT();
            CP_WAIT1();
        } else {
            asm volatile("cp.async.wait_group 0;" ::: "memory");
        }
        __syncthreads();
        compute_chunk(smem, c & 1, wm, wn, lane, acc);
    }

    // epilogue -> fp32 g_part
#pragma unroll
    for (int mf = 0; mf < 4; mf++) {
        int r0 = m0 + wm * 64 + mf * 16 + (lane >> 2);
        float* d0 = g_part + ((size_t)p * NPOS + r0) * DM + n0;
        float* d1 = d0 + 8 * DM;
#pragma unroll
        for (int nf = 0; nf < 4; nf++) {
            int c0 = wn * 32 + nf * 8 + (lane & 3) * 2;
            float2 v0 = { acc[mf][nf][0], acc[mf][nf][1] };
            float2 v1 = { acc[mf][nf][2], acc[mf][nf][3] };
            *(float2*)(d0 + c0) = v0;
            *(float2*)(d1 + c0) = v1;
        }
    }
}

// ---------------------------------------------------------------------------
// Fixed-order reduction over sources + bias. grid (NPOS*DM/1024, NL)
// ---------------------------------------------------------------------------
__global__ __launch_bounds__(256, 4)
void reduce_out(const float* __restrict__ b_dec, float* __restrict__ out) {
    const int jj = blockIdx.y;
    const int base = jj * (jj + 1) / 2;
    size_t lin = ((size_t)blockIdx.x * 256 + threadIdx.x) * 4;
    int d = (int)(lin % DM);
    float4 acc = *(const float4*)(b_dec + (size_t)jj * DM + d);
    for (int i = 0; i <= jj; i++) {
        float4 v = *(const float4*)(g_part + (size_t)(base + i) * NPOS * DM + lin);
        acc.x += v.x; acc.y += v.y; acc.z += v.z; acc.w += v.w;
    }
    *(float4*)(out + (size_t)jj * NPOS * DM + lin) = acc;
}

// ---------------------------------------------------------------------------
extern "C" void kernel_launch(void* const* d_in, const int* in_sizes, int n_in,
                              void* d_out, int out_size) {
    const float* x     = (const float*)d_in[0];
    const float* W_enc = (const float*)d_in[1];
    const float* b_enc = (const float*)d_in[2];
    const float* W_dec = (const float*)d_in[3];
    const float* b_dec = (const float*)d_in[4];
    float* out = (float*)d_out;

    static cudaStream_t s2 = nullptr;
    static cudaEvent_t evA = nullptr, evB = nullptr;
    if (!s2) {
        cudaFuncSetAttribute(encode_tc, cudaFuncAttributeMaxDynamicSharedMemorySize, SMEM_BYTES);
        cudaFuncSetAttribute(decode_tc, cudaFuncAttributeMaxDynamicSharedMemorySize, SMEM_BYTES);
        cudaStreamCreateWithFlags(&s2, cudaStreamNonBlocking);
        cudaEventCreateWithFlags(&evA, cudaEventDisableTiming);
        cudaEventCreateWithFlags(&evB, cudaEventDisableTiming);
    }

    __half* g_xr_p;   cudaGetSymbolAddress((void**)&g_xr_p,  g_xr);
    __half* g_wer_p;  cudaGetSymbolAddress((void**)&g_wer_p, g_wer);

    // Fork: W_dec transpose+convert on side stream, overlapped with encode chain.
    cudaEventRecord(evA, 0);
    cudaStreamWaitEvent(s2, evA, 0);
    wdec_T<<<dim3(FT / 32, DM / 32, NPAIR), dim3(32, 8), 0, s2>>>(W_dec);
    cudaEventRecord(evB, s2);

    half_copy<<<(NL * NPOS * DM) / 2048, 256>>>(x, g_xr_p);
    half_copy<<<(NL * FT * DM) / 2048, 256>>>(W_enc, g_wer_p);
    encode_tc<<<dim3(FT / 128, NPOS / 128, NL), NT, SMEM_BYTES>>>(b_enc);

    // Join, then decode + reduce.
    cudaStreamWaitEvent(0, evB, 0);
    decode_tc<<<dim3(DM / 128, NPOS / 128, NPAIR), NT, SMEM_BYTES>>>();
    reduce_out<<<dim3(NPOS * DM / 1024, NL), 256>>>(b_dec, out);
}

// round 12
// speedup vs baseline: 2.1058x; 1.0406x over previous
#include <cuda_runtime.h>
#include <cuda_fp16.h>
#include <cstdint>

#define NL    8
#define NPOS  1024
#define DM    768
#define FT    4096
#define NPAIR 36
#define NT    256           // 8 warps: 2(M) x 4(N) grid of 64x32 warp tiles

// ---------------------------------------------------------------------------
// Static device scratch (half precision planes)
// ---------------------------------------------------------------------------
__device__ __half g_xr  [(size_t)NL * NPOS * DM];       // 12.5 MB
__device__ __half g_wer [(size_t)NL * FT * DM];         //  50 MB
__device__ __half g_wdT [(size_t)NPAIR * DM * FT];      // 226 MB  [p][d][f]
__device__ __half g_feats[(size_t)NL * NPOS * FT];      //  67 MB
__device__ float  g_part[(size_t)NPAIR * NPOS * DM];    // 113 MB  fp32 partials

// ---------------------------------------------------------------------------
// Helpers
// ---------------------------------------------------------------------------
__device__ __forceinline__ uint32_t smem_u32(const void* p) {
    uint32_t a;
    asm("{ .reg .u64 t; cvta.to.shared.u64 t, %1; cvt.u32.u64 %0, t; }" : "=r"(a) : "l"(p));
    return a;
}
#define CP_ASYNC16(dst, src) \
    asm volatile("cp.async.cg.shared.global [%0], [%1], 16;" :: "r"(dst), "l"(src))
#define CP_COMMIT() asm volatile("cp.async.commit_group;" ::: "memory")
#define CP_WAIT1()  asm volatile("cp.async.wait_group 1;" ::: "memory")

__device__ __forceinline__ void mma_f16(float c[4],
                                        unsigned a0, unsigned a1, unsigned a2, unsigned a3,
                                        unsigned b0, unsigned b1) {
    asm volatile(
        "mma.sync.aligned.m16n8k16.row.col.f32.f16.f16.f32 "
        "{%0,%1,%2,%3}, {%4,%5,%6,%7}, {%8,%9}, {%0,%1,%2,%3};"
        : "+f"(c[0]), "+f"(c[1]), "+f"(c[2]), "+f"(c[3])
        : "r"(a0), "r"(a1), "r"(a2), "r"(a3), "r"(b0), "r"(b1));
}
__device__ __forceinline__ void ldsm4(unsigned r[4], uint32_t addr) {
    asm volatile("ldmatrix.sync.aligned.m8n8.x4.shared.b16 {%0,%1,%2,%3}, [%4];"
        : "=r"(r[0]), "=r"(r[1]), "=r"(r[2]), "=r"(r[3]) : "r"(addr));
}

// ---------------------------------------------------------------------------
// SMEM: 2 stages, K-chunk 64 halves.
//   A tile 128 x 64 halves, row stride 72 halves (144 B)   = 18432 B
//   B tile 128 x 64 halves, row stride 72 halves           = 18432 B
// Both [row][k], k contiguous (W_dec pre-transposed).
// ---------------------------------------------------------------------------
#define STAGES 2
#define KC    64
#define HSTR  72
#define ROWB  (HSTR * 2)                  // 144 bytes per row
#define A_BYTES (128 * ROWB)              // 18432
#define B_OFF   A_BYTES
#define B_BYTES (128 * ROWB)              // 18432
#define STAGE   (A_BYTES + B_BYTES)       // 36864
#define SMEM_BYTES (STAGES * STAGE)       // 73728 per CTA (x2 CTAs = 147456)

// tile loader: 128 rows x 64 halves (8 x 16B per row); gstr in halves
__device__ __forceinline__ void load_tile(const __half* __restrict__ src, size_t gstr,
                                          uint32_t dst, int tid) {
#pragma unroll
    for (int q = 0; q < 4; q++) {
        int idx = tid + q * NT;
        int row = idx >> 3, seg = idx & 7;
        CP_ASYNC16(dst + row * ROWB + seg * 16, src + (size_t)row * gstr + seg * 8);
    }
}

// compute one K=64 chunk = 4 kk-steps of K=16; warp tile 64(M) x 32(N).
// All fragments via ldmatrix.x4 (canonical fp16 patterns).
__device__ __forceinline__ void compute_chunk(uint32_t sA, uint32_t sB,
                                              uint32_t a_off, uint32_t b_off,
                                              float acc[4][4][4]) {
#pragma unroll
    for (int kk = 0; kk < 4; kk++) {
        unsigned a[4][4], b[2][4];
#pragma unroll
        for (int mf = 0; mf < 4; mf++)
            ldsm4(a[mf], sA + mf * (16 * ROWB) + a_off + kk * 32);
#pragma unroll
        for (int p = 0; p < 2; p++)
            ldsm4(b[p], sB + p * (16 * ROWB) + b_off + kk * 32);
#pragma unroll
        for (int mf = 0; mf < 4; mf++)
#pragma unroll
            for (int p = 0; p < 2; p++) {
                mma_f16(acc[mf][2 * p],     a[mf][0], a[mf][1], a[mf][2], a[mf][3],
                        b[p][0], b[p][1]);
                mma_f16(acc[mf][2 * p + 1], a[mf][0], a[mf][1], a[mf][2], a[mf][3],
                        b[p][2], b[p][3]);
            }
    }
}

// ---------------------------------------------------------------------------
// Prep kernels
// ---------------------------------------------------------------------------
__global__ void half_copy(const float* __restrict__ src, __half* __restrict__ dst) {
    size_t i = ((size_t)blockIdx.x * 256 + threadIdx.x) * 8;
    float4 v0 = *(const float4*)(src + i);
    float4 v1 = *(const float4*)(src + i + 4);
    __half2 h[4] = { __floats2half2_rn(v0.x, v0.y), __floats2half2_rn(v0.z, v0.w),
                     __floats2half2_rn(v1.x, v1.y), __floats2half2_rn(v1.z, v1.w) };
    *(uint4*)(dst + i) = *(uint4*)h;
}
// W_dec[i,j][f][d] -> g_wdT[p][d][f], half
__global__ void wdec_T(const float* __restrict__ W_dec) {
    int p = blockIdx.z;
    int j = 0, a = 0;
    while (a + j + 1 <= p) { a += j + 1; ++j; }
    int i = p - a;
    int f0 = blockIdx.x * 32, d0 = blockIdx.y * 32;
    int tx = threadIdx.x, ty = threadIdx.y;
    __shared__ float t[32][33];
    const float* src = W_dec + (size_t)(i * NL + j) * FT * DM;
#pragma unroll
    for (int r = 0; r < 4; r++)
        t[ty + r * 8][tx] = src[(size_t)(f0 + ty + r * 8) * DM + d0 + tx];
    __syncthreads();
    __half* dst = g_wdT + (size_t)p * DM * FT;
#pragma unroll
    for (int r = 0; r < 4; r++)
        dst[(size_t)(d0 + ty + r * 8) * FT + f0 + tx] = __float2half_rn(t[tx][ty + r * 8]);
}

// ---------------------------------------------------------------------------
// Encoder: feats = relu(x @ W_enc^T + b_enc) -> half. grid (FT/128, NPOS/128, NL)
// ---------------------------------------------------------------------------
__global__ __launch_bounds__(NT, 2)
void encode_tc(const float* __restrict__ b_enc) {
    extern __shared__ float smem[];
    const int l = blockIdx.z, m0 = blockIdx.y * 128, n0 = blockIdx.x * 128;
    const int tid = threadIdx.x, lane = tid & 31, warp = tid >> 5;
    const int wm = warp & 1, wn = warp >> 1;   // 2 x 4 warp grid
    const uint32_t sb = smem_u32(smem);

    // ldmatrix per-thread address components (bytes)
    const uint32_t a_off = (wm * 64 + (lane & 15)) * ROWB + (lane >> 4) * 16;
    const uint32_t b_off = (wn * 32 + (lane & 7) + ((lane >> 4) << 3)) * ROWB
                         + ((lane >> 3) & 1) * 16;

    float acc[4][4][4];
#pragma unroll
    for (int a = 0; a < 4; a++)
#pragma unroll
        for (int b = 0; b < 4; b++)
#pragma unroll
            for (int c = 0; c < 4; c++) acc[a][b][c] = 0.f;

    const __half* abase = g_xr  + ((size_t)l * NPOS + m0) * DM;
    const __half* bbase = g_wer + ((size_t)l * FT + n0) * DM;
    const int NC = DM / KC;     // 12

    load_tile(abase, DM, sb, tid);
    load_tile(bbase, DM, sb + B_OFF, tid);
    CP_COMMIT();
    for (int c = 0; c < NC; c++) {
        int nc = c + 1;
        if (nc < NC) {
            uint32_t s = sb + (nc & 1) * STAGE;
            if (c > 0) { CP_WAIT1(); __syncthreads(); }
            load_tile(abase + nc * KC, DM, s, tid);
            load_tile(bbase + nc * KC, DM, s + B_OFF, tid);
            CP_COMMIT();
            CP_WAIT1();
        } else {
            asm volatile("cp.async.wait_group 0;" ::: "memory");
        }
        __syncthreads();
        uint32_t st = sb + (c & 1) * STAGE;
        compute_chunk(st, st + B_OFF, a_off, b_off, acc);
    }

    // epilogue: bias + relu -> half g_feats
    const float* be = b_enc + (size_t)l * FT + n0;
#pragma unroll
    for (int mf = 0; mf < 4; mf++) {
        int r0 = m0 + wm * 64 + mf * 16 + (lane >> 2);
        __half* d0 = g_feats + ((size_t)l * NPOS + r0) * FT + n0;
        __half* d1 = d0 + 8 * FT;
#pragma unroll
        for (int nf = 0; nf < 4; nf++) {
            int c0 = wn * 32 + nf * 8 + (lane & 3) * 2;
            float b0 = be[c0], b1 = be[c0 + 1];
            __half2 v0 = __floats2half2_rn(fmaxf(acc[mf][nf][0] + b0, 0.f),
                                           fmaxf(acc[mf][nf][1] + b1, 0.f));
            __half2 v1 = __floats2half2_rn(fmaxf(acc[mf][nf][2] + b0, 0.f),
                                           fmaxf(acc[mf][nf][3] + b1, 0.f));
            *(__half2*)(d0 + c0) = v0;
            *(__half2*)(d1 + c0) = v1;
        }
    }
}

// ---------------------------------------------------------------------------
// Decoder partials: g_part[p] = feats[i] @ W_dec[i,j]. grid (DM/128, NPOS/128, NPAIR)
// ---------------------------------------------------------------------------
__global__ __launch_bounds__(NT, 2)
void decode_tc() {
    extern __shared__ float smem[];
    const int p = blockIdx.z, m0 = blockIdx.y * 128, n0 = blockIdx.x * 128;
    int j = 0, a0 = 0;
    while (a0 + j + 1 <= p) { a0 += j + 1; ++j; }
    const int i = p - a0;
    const int tid = threadIdx.x, lane = tid & 31, warp = tid >> 5;
    const int wm = warp & 1, wn = warp >> 1;
    const uint32_t sb = smem_u32(smem);

    const uint32_t a_off = (wm * 64 + (lane & 15)) * ROWB + (lane >> 4) * 16;
    const uint32_t b_off = (wn * 32 + (lane & 7) + ((lane >> 4) << 3)) * ROWB
                         + ((lane >> 3) & 1) * 16;

    float acc[4][4][4];
#pragma unroll
    for (int a = 0; a < 4; a++)
#pragma unroll
        for (int b = 0; b < 4; b++)
#pragma unroll
            for (int c = 0; c < 4; c++) acc[a][b][c] = 0.f;

    const __half* abase = g_feats + ((size_t)i * NPOS + m0) * FT;
    const __half* bbase = g_wdT + (size_t)p * DM * FT + (size_t)n0 * FT;
    const int NC = FT / KC;     // 64

    load_tile(abase, FT, sb, tid);
    load_tile(bbase, FT, sb + B_OFF, tid);
    CP_COMMIT();
    for (int c = 0; c < NC; c++) {
        int nc = c + 1;
        if (nc < NC) {
            uint32_t s = sb + (nc & 1) * STAGE;
            if (c > 0) { CP_WAIT1(); __syncthreads(); }
            load_tile(abase + nc * KC, FT, s, tid);
            load_tile(bbase + nc * KC, FT, s + B_OFF, tid);
            CP_COMMIT();
            CP_WAIT1();
        } else {
            asm volatile("cp.async.wait_group 0;" ::: "memory");
        }
        __syncthreads();
        uint32_t st = sb + (c & 1) * STAGE;
        compute_chunk(st, st + B_OFF, a_off, b_off, acc);
    }

    // epilogue -> fp32 g_part
#pragma unroll
    for (int mf = 0; mf < 4; mf++) {
        int r0 = m0 + wm * 64 + mf * 16 + (lane >> 2);
        float* d0 = g_part + ((size_t)p * NPOS + r0) * DM + n0;
        float* d1 = d0 + 8 * DM;
#pragma unroll
        for (int nf = 0; nf < 4; nf++) {
            int c0 = wn * 32 + nf * 8 + (lane & 3) * 2;
            float2 v0 = { acc[mf][nf][0], acc[mf][nf][1] };
            float2 v1 = { acc[mf][nf][2], acc[mf][nf][3] };
            *(float2*)(d0 + c0) = v0;
            *(float2*)(d1 + c0) = v1;
        }
    }
}

// ---------------------------------------------------------------------------
// Fixed-order reduction over sources + bias. grid (NPOS*DM/1024, NL)
// ---------------------------------------------------------------------------
__global__ __launch_bounds__(256, 4)
void reduce_out(const float* __restrict__ b_dec, float* __restrict__ out) {
    const int jj = blockIdx.y;
    const int base = jj * (jj + 1) / 2;
    size_t lin = ((size_t)blockIdx.x * 256 + threadIdx.x) * 4;
    int d = (int)(lin % DM);
    float4 acc = *(const float4*)(b_dec + (size_t)jj * DM + d);
    for (int i = 0; i <= jj; i++) {
        float4 v = *(const float4*)(g_part + (size_t)(base + i) * NPOS * DM + lin);
        acc.x += v.x; acc.y += v.y; acc.z += v.z; acc.w += v.w;
    }
    *(float4*)(out + (size_t)jj * NPOS * DM + lin) = acc;
}

// ---------------------------------------------------------------------------
extern "C" void kernel_launch(void* const* d_in, const int* in_sizes, int n_in,
                              void* d_out, int out_size) {
    const float* x     = (const float*)d_in[0];
    const float* W_enc = (const float*)d_in[1];
    const float* b_enc = (const float*)d_in[2];
    const float* W_dec = (const float*)d_in[3];
    const float* b_dec = (const float*)d_in[4];
    float* out = (float*)d_out;

    static cudaStream_t s2 = nullptr;
    static cudaEvent_t evA = nullptr, evB = nullptr;
    if (!s2) {
        cudaFuncSetAttribute(encode_tc, cudaFuncAttributeMaxDynamicSharedMemorySize, SMEM_BYTES);
        cudaFuncSetAttribute(decode_tc, cudaFuncAttributeMaxDynamicSharedMemorySize, SMEM_BYTES);
        cudaStreamCreateWithFlags(&s2, cudaStreamNonBlocking);
        cudaEventCreateWithFlags(&evA, cudaEventDisableTiming);
        cudaEventCreateWithFlags(&evB, cudaEventDisableTiming);
    }

    __half* g_xr_p;   cudaGetSymbolAddress((void**)&g_xr_p,  g_xr);
    __half* g_wer_p;  cudaGetSymbolAddress((void**)&g_wer_p, g_wer);

    // Fork: W_dec transpose+convert on side stream, overlapped with encode chain.
    cudaEventRecord(evA, 0);
    cudaStreamWaitEvent(s2, evA, 0);
    wdec_T<<<dim3(FT / 32, DM / 32, NPAIR), dim3(32, 8), 0, s2>>>(W_dec);
    cudaEventRecord(evB, s2);

    half_copy<<<(NL * NPOS * DM) / 2048, 256>>>(x, g_xr_p);
    half_copy<<<(NL * FT * DM) / 2048, 256>>>(W_enc, g_wer_p);
    encode_tc<<<dim3(FT / 128, NPOS / 128, NL), NT, SMEM_BYTES>>>(b_enc);

    // Join, then decode + reduce.
    cudaStreamWaitEvent(0, evB, 0);
    decode_tc<<<dim3(DM / 128, NPOS / 128, NPAIR), NT, SMEM_BYTES>>>();
    reduce_out<<<dim3(NPOS * DM / 1024, NL), 256>>>(b_dec, out);
}

// round 13
// speedup vs baseline: 2.1191x; 1.0063x over previous
#include <cuda_runtime.h>
#include <cuda_fp16.h>
#include <cstdint>

#define NL    8
#define NPOS  1024
#define DM    768
#define FT    4096
#define NPAIR 36
#define NT    256           // 8 warps: 2(M) x 4(N) grid of 64x32 warp tiles

// ---------------------------------------------------------------------------
// Static device scratch (half precision planes)
// ---------------------------------------------------------------------------
__device__ __half g_xr  [(size_t)NL * NPOS * DM];       // 12.5 MB
__device__ __half g_wer [(size_t)NL * FT * DM];         //  50 MB
__device__ __half g_wdT [(size_t)NPAIR * DM * FT];      // 226 MB  [p][d][f]
__device__ __half g_feats[(size_t)NL * NPOS * FT];      //  67 MB
__device__ float  g_part[(size_t)NPAIR * NPOS * DM];    // 113 MB  fp32 partials

// ---------------------------------------------------------------------------
// Helpers
// ---------------------------------------------------------------------------
__device__ __forceinline__ uint32_t smem_u32(const void* p) {
    uint32_t a;
    asm("{ .reg .u64 t; cvta.to.shared.u64 t, %1; cvt.u32.u64 %0, t; }" : "=r"(a) : "l"(p));
    return a;
}
#define CP_ASYNC16(dst, src) \
    asm volatile("cp.async.cg.shared.global [%0], [%1], 16;" :: "r"(dst), "l"(src))
#define CP_COMMIT() asm volatile("cp.async.commit_group;" ::: "memory")
#define CP_WAIT1()  asm volatile("cp.async.wait_group 1;" ::: "memory")
#define CP_WAIT0()  asm volatile("cp.async.wait_group 0;" ::: "memory")

__device__ __forceinline__ void mma_f16(float c[4],
                                        unsigned a0, unsigned a1, unsigned a2, unsigned a3,
                                        unsigned b0, unsigned b1) {
    asm volatile(
        "mma.sync.aligned.m16n8k16.row.col.f32.f16.f16.f32 "
        "{%0,%1,%2,%3}, {%4,%5,%6,%7}, {%8,%9}, {%0,%1,%2,%3};"
        : "+f"(c[0]), "+f"(c[1]), "+f"(c[2]), "+f"(c[3])
        : "r"(a0), "r"(a1), "r"(a2), "r"(a3), "r"(b0), "r"(b1));
}
__device__ __forceinline__ void ldsm4(unsigned r[4], uint32_t addr) {
    asm volatile("ldmatrix.sync.aligned.m8n8.x4.shared.b16 {%0,%1,%2,%3}, [%4];"
        : "=r"(r[0]), "=r"(r[1]), "=r"(r[2]), "=r"(r[3]) : "r"(addr));
}

// ---------------------------------------------------------------------------
// SMEM: 3 stages, K-chunk 64 halves.
//   A tile 128 x 64 halves, row stride 72 halves (144 B)   = 18432 B
//   B tile 128 x 64 halves, row stride 72 halves           = 18432 B
// Both [row][k], k contiguous (W_dec pre-transposed).
// ---------------------------------------------------------------------------
#define STAGES 3
#define KC    64
#define HSTR  72
#define ROWB  (HSTR * 2)                  // 144 bytes per row
#define A_BYTES (128 * ROWB)              // 18432
#define B_OFF   A_BYTES
#define B_BYTES (128 * ROWB)              // 18432
#define STAGE   (A_BYTES + B_BYTES)       // 36864
#define SMEM_BYTES (STAGES * STAGE)       // 110592 per CTA (x2 CTAs = 221184)

// tile loader: 128 rows x 64 halves (8 x 16B per row); gstr in halves
__device__ __forceinline__ void load_tile(const __half* __restrict__ src, size_t gstr,
                                          uint32_t dst, int tid) {
#pragma unroll
    for (int q = 0; q < 4; q++) {
        int idx = tid + q * NT;
        int row = idx >> 3, seg = idx & 7;
        CP_ASYNC16(dst + row * ROWB + seg * 16, src + (size_t)row * gstr + seg * 8);
    }
}

// compute one K=64 chunk = 4 kk-steps of K=16; warp tile 64(M) x 32(N).
// All fragments via ldmatrix.x4 (canonical fp16 patterns).
__device__ __forceinline__ void compute_chunk(uint32_t sA, uint32_t sB,
                                              uint32_t a_off, uint32_t b_off,
                                              float acc[4][4][4]) {
#pragma unroll
    for (int kk = 0; kk < 4; kk++) {
        unsigned a[4][4], b[2][4];
#pragma unroll
        for (int mf = 0; mf < 4; mf++)
            ldsm4(a[mf], sA + mf * (16 * ROWB) + a_off + kk * 32);
#pragma unroll
        for (int p = 0; p < 2; p++)
            ldsm4(b[p], sB + p * (16 * ROWB) + b_off + kk * 32);
#pragma unroll
        for (int mf = 0; mf < 4; mf++)
#pragma unroll
            for (int p = 0; p < 2; p++) {
                mma_f16(acc[mf][2 * p],     a[mf][0], a[mf][1], a[mf][2], a[mf][3],
                        b[p][0], b[p][1]);
                mma_f16(acc[mf][2 * p + 1], a[mf][0], a[mf][1], a[mf][2], a[mf][3],
                        b[p][2], b[p][3]);
            }
    }
}

// ---------------------------------------------------------------------------
// Prep kernels
// ---------------------------------------------------------------------------
__global__ void half_copy(const float* __restrict__ src, __half* __restrict__ dst) {
    size_t i = ((size_t)blockIdx.x * 256 + threadIdx.x) * 8;
    float4 v0 = *(const float4*)(src + i);
    float4 v1 = *(const float4*)(src + i + 4);
    __half2 h[4] = { __floats2half2_rn(v0.x, v0.y), __floats2half2_rn(v0.z, v0.w),
                     __floats2half2_rn(v1.x, v1.y), __floats2half2_rn(v1.z, v1.w) };
    *(uint4*)(dst + i) = *(uint4*)h;
}
// W_dec[i,j][f][d] -> g_wdT[p][d][f], half
__global__ void wdec_T(const float* __restrict__ W_dec) {
    int p = blockIdx.z;
    int j = 0, a = 0;
    while (a + j + 1 <= p) { a += j + 1; ++j; }
    int i = p - a;
    int f0 = blockIdx.x * 32, d0 = blockIdx.y * 32;
    int tx = threadIdx.x, ty = threadIdx.y;
    __shared__ float t[32][33];
    const float* src = W_dec + (size_t)(i * NL + j) * FT * DM;
#pragma unroll
    for (int r = 0; r < 4; r++)
        t[ty + r * 8][tx] = src[(size_t)(f0 + ty + r * 8) * DM + d0 + tx];
    __syncthreads();
    __half* dst = g_wdT + (size_t)p * DM * FT;
#pragma unroll
    for (int r = 0; r < 4; r++)
        dst[(size_t)(d0 + ty + r * 8) * FT + f0 + tx] = __float2half_rn(t[tx][ty + r * 8]);
}

// ---------------------------------------------------------------------------
// Encoder: feats = relu(x @ W_enc^T + b_enc) -> half. grid (FT/128, NPOS/128, NL)
// ---------------------------------------------------------------------------
__global__ __launch_bounds__(NT, 2)
void encode_tc(const float* __restrict__ b_enc) {
    extern __shared__ float smem[];
    const int l = blockIdx.z, m0 = blockIdx.y * 128, n0 = blockIdx.x * 128;
    const int tid = threadIdx.x, lane = tid & 31, warp = tid >> 5;
    const int wm = warp & 1, wn = warp >> 1;   // 2 x 4 warp grid
    const uint32_t sb = smem_u32(smem);

    // ldmatrix per-thread address components (bytes)
    const uint32_t a_off = (wm * 64 + (lane & 15)) * ROWB + (lane >> 4) * 16;
    const uint32_t b_off = (wn * 32 + (lane & 7) + ((lane >> 4) << 3)) * ROWB
                         + ((lane >> 3) & 1) * 16;

    float acc[4][4][4];
#pragma unroll
    for (int a = 0; a < 4; a++)
#pragma unroll
        for (int b = 0; b < 4; b++)
#pragma unroll
            for (int c = 0; c < 4; c++) acc[a][b][c] = 0.f;

    const __half* abase = g_xr  + ((size_t)l * NPOS + m0) * DM;
    const __half* bbase = g_wer + ((size_t)l * FT + n0) * DM;
    const int NC = DM / KC;     // 12

    // prologue: stages 0 and 1
    load_tile(abase, DM, sb, tid);
    load_tile(bbase, DM, sb + B_OFF, tid);
    CP_COMMIT();
    load_tile(abase + KC, DM, sb + STAGE, tid);
    load_tile(bbase + KC, DM, sb + STAGE + B_OFF, tid);
    CP_COMMIT();

    for (int c = 0; c < NC; c++) {
        if (c + 1 < NC) { CP_WAIT1(); } else { CP_WAIT0(); }
        __syncthreads();
        int nc = c + 2;
        if (nc < NC) {
            uint32_t s = sb + (nc % STAGES) * STAGE;
            load_tile(abase + nc * KC, DM, s, tid);
            load_tile(bbase + nc * KC, DM, s + B_OFF, tid);
            CP_COMMIT();
        }
        uint32_t st = sb + (c % STAGES) * STAGE;
        compute_chunk(st, st + B_OFF, a_off, b_off, acc);
    }

    // epilogue: bias + relu -> half g_feats
    const float* be = b_enc + (size_t)l * FT + n0;
#pragma unroll
    for (int mf = 0; mf < 4; mf++) {
        int r0 = m0 + wm * 64 + mf * 16 + (lane >> 2);
        __half* d0 = g_feats + ((size_t)l * NPOS + r0) * FT + n0;
        __half* d1 = d0 + 8 * FT;
#pragma unroll
        for (int nf = 0; nf < 4; nf++) {
            int c0 = wn * 32 + nf * 8 + (lane & 3) * 2;
            float b0 = be[c0], b1 = be[c0 + 1];
            __half2 v0 = __floats2half2_rn(fmaxf(acc[mf][nf][0] + b0, 0.f),
                                           fmaxf(acc[mf][nf][1] + b1, 0.f));
            __half2 v1 = __floats2half2_rn(fmaxf(acc[mf][nf][2] + b0, 0.f),
                                           fmaxf(acc[mf][nf][3] + b1, 0.f));
            *(__half2*)(d0 + c0) = v0;
            *(__half2*)(d1 + c0) = v1;
        }
    }
}

// ---------------------------------------------------------------------------
// Decoder partials: g_part[p] = feats[i] @ W_dec[i,j]. grid (DM/128, NPOS/128, NPAIR)
// ---------------------------------------------------------------------------
__global__ __launch_bounds__(NT, 2)
void decode_tc() {
    extern __shared__ float smem[];
    const int p = blockIdx.z, m0 = blockIdx.y * 128, n0 = blockIdx.x * 128;
    int j = 0, a0 = 0;
    while (a0 + j + 1 <= p) { a0 += j + 1; ++j; }
    const int i = p - a0;
    const int tid = threadIdx.x, lane = tid & 31, warp = tid >> 5;
    const int wm = warp & 1, wn = warp >> 1;
    const uint32_t sb = smem_u32(smem);

    const uint32_t a_off = (wm * 64 + (lane & 15)) * ROWB + (lane >> 4) * 16;
    const uint32_t b_off = (wn * 32 + (lane & 7) + ((lane >> 4) << 3)) * ROWB
                         + ((lane >> 3) & 1) * 16;

    float acc[4][4][4];
#pragma unroll
    for (int a = 0; a < 4; a++)
#pragma unroll
        for (int b = 0; b < 4; b++)
#pragma unroll
            for (int c = 0; c < 4; c++) acc[a][b][c] = 0.f;

    const __half* abase = g_feats + ((size_t)i * NPOS + m0) * FT;
    const __half* bbase = g_wdT + (size_t)p * DM * FT + (size_t)n0 * FT;
    const int NC = FT / KC;     // 64

    load_tile(abase, FT, sb, tid);
    load_tile(bbase, FT, sb + B_OFF, tid);
    CP_COMMIT();
    load_tile(abase + KC, FT, sb + STAGE, tid);
    load_tile(bbase + KC, FT, sb + STAGE + B_OFF, tid);
    CP_COMMIT();

    for (int c = 0; c < NC; c++) {
        if (c + 1 < NC) { CP_WAIT1(); } else { CP_WAIT0(); }
        __syncthreads();
        int nc = c + 2;
        if (nc < NC) {
            uint32_t s = sb + (nc % STAGES) * STAGE;
            load_tile(abase + nc * KC, FT, s, tid);
            load_tile(bbase + nc * KC, FT, s + B_OFF, tid);
            CP_COMMIT();
        }
        uint32_t st = sb + (c % STAGES) * STAGE;
        compute_chunk(st, st + B_OFF, a_off, b_off, acc);
    }

    // epilogue -> fp32 g_part
#pragma unroll
    for (int mf = 0; mf < 4; mf++) {
        int r0 = m0 + wm * 64 + mf * 16 + (lane >> 2);
        float* d0 = g_part + ((size_t)p * NPOS + r0) * DM + n0;
        float* d1 = d0 + 8 * DM;
#pragma unroll
        for (int nf = 0; nf < 4; nf++) {
            int c0 = wn * 32 + nf * 8 + (lane & 3) * 2;
            float2 v0 = { acc[mf][nf][0], acc[mf][nf][1] };
            float2 v1 = { acc[mf][nf][2], acc[mf][nf][3] };
            *(float2*)(d0 + c0) = v0;
            *(float2*)(d1 + c0) = v1;
        }
    }
}

// ---------------------------------------------------------------------------
// Fixed-order reduction over sources + bias. grid (NPOS*DM/1024, NL)
// ---------------------------------------------------------------------------
__global__ __launch_bounds__(256, 4)
void reduce_out(const float* __restrict__ b_dec, float* __restrict__ out) {
    const int jj = blockIdx.y;
    const int base = jj * (jj + 1) / 2;
    size_t lin = ((size_t)blockIdx.x * 256 + threadIdx.x) * 4;
    int d = (int)(lin % DM);
    float4 acc = *(const float4*)(b_dec + (size_t)jj * DM + d);
    for (int i = 0; i <= jj; i++) {
        float4 v = *(const float4*)(g_part + (size_t)(base + i) * NPOS * DM + lin);
        acc.x += v.x; acc.y += v.y; acc.z += v.z; acc.w += v.w;
    }
    *(float4*)(out + (size_t)jj * NPOS * DM + lin) = acc;
}

// ---------------------------------------------------------------------------
extern "C" void kernel_launch(void* const* d_in, const int* in_sizes, int n_in,
                              void* d_out, int out_size) {
    const float* x     = (const float*)d_in[0];
    const float* W_enc = (const float*)d_in[1];
    const float* b_enc = (const float*)d_in[2];
    const float* W_dec = (const float*)d_in[3];
    const float* b_dec = (const float*)d_in[4];
    float* out = (float*)d_out;

    static cudaStream_t s2 = nullptr;
    static cudaEvent_t evA = nullptr, evB = nullptr;
    if (!s2) {
        cudaFuncSetAttribute(encode_tc, cudaFuncAttributeMaxDynamicSharedMemorySize, SMEM_BYTES);
        cudaFuncSetAttribute(decode_tc, cudaFuncAttributeMaxDynamicSharedMemorySize, SMEM_BYTES);
        cudaStreamCreateWithFlags(&s2, cudaStreamNonBlocking);
        cudaEventCreateWithFlags(&evA, cudaEventDisableTiming);
        cudaEventCreateWithFlags(&evB, cudaEventDisableTiming);
    }

    __half* g_xr_p;   cudaGetSymbolAddress((void**)&g_xr_p,  g_xr);
    __half* g_wer_p;  cudaGetSymbolAddress((void**)&g_wer_p, g_wer);

    // Fork: W_dec transpose+convert on side stream, overlapped with encode chain.
    cudaEventRecord(evA, 0);
    cudaStreamWaitEvent(s2, evA, 0);
    wdec_T<<<dim3(FT / 32, DM / 32, NPAIR), dim3(32, 8), 0, s2>>>(W_dec);
    cudaEventRecord(evB, s2);

    half_copy<<<(NL * NPOS * DM) / 2048, 256>>>(x, g_xr_p);
    half_copy<<<(NL * FT * DM) / 2048, 256>>>(W_enc, g_wer_p);
    encode_tc<<<dim3(FT / 128, NPOS / 128, NL), NT, SMEM_BYTES>>>(b_enc);

    // Join, then decode + reduce.
    cudaStreamWaitEvent(0, evB, 0);
    decode_tc<<<dim3(DM / 128, NPOS / 128, NPAIR), NT, SMEM_BYTES>>>();
    reduce_out<<<dim3(NPOS * DM / 1024, NL), 256>>>(b_dec, out);
}

// round 14
// speedup vs baseline: 2.1339x; 1.0070x over previous
#include <cuda_runtime.h>
#include <cuda_fp16.h>
#include <cstdint>

#define NL    8
#define NPOS  1024
#define DM    768
#define FT    4096
#define NPAIR 36
#define NT    256           // 8 warps: 2(M) x 4(N) grid of 64x32 warp tiles

// ---------------------------------------------------------------------------
// Static device scratch
// ---------------------------------------------------------------------------
__device__ __half g_xr  [(size_t)NL * NPOS * DM];       // 12.5 MB
__device__ __half g_wer [(size_t)NL * FT * DM];         //  50 MB
__device__ __half g_wdT [(size_t)NPAIR * DM * FT];      // 226 MB  [p][d][f]
__device__ __half g_feats[(size_t)NL * NPOS * FT];      //  67 MB
__device__ float  g_part[(size_t)NPAIR * NPOS * DM];    // 113 MB  fp32 partials
__device__ int    g_pair_done[NPAIR];                   // decode->reduce gating

// ---------------------------------------------------------------------------
// Helpers
// ---------------------------------------------------------------------------
__device__ __forceinline__ uint32_t smem_u32(const void* p) {
    uint32_t a;
    asm("{ .reg .u64 t; cvta.to.shared.u64 t, %1; cvt.u32.u64 %0, t; }" : "=r"(a) : "l"(p));
    return a;
}
#define CP_ASYNC16(dst, src) \
    asm volatile("cp.async.cg.shared.global [%0], [%1], 16;" :: "r"(dst), "l"(src))
#define CP_COMMIT() asm volatile("cp.async.commit_group;" ::: "memory")
#define CP_WAIT1()  asm volatile("cp.async.wait_group 1;" ::: "memory")
#define CP_WAIT0()  asm volatile("cp.async.wait_group 0;" ::: "memory")

__device__ __forceinline__ void mma_f16(float c[4],
                                        unsigned a0, unsigned a1, unsigned a2, unsigned a3,
                                        unsigned b0, unsigned b1) {
    asm volatile(
        "mma.sync.aligned.m16n8k16.row.col.f32.f16.f16.f32 "
        "{%0,%1,%2,%3}, {%4,%5,%6,%7}, {%8,%9}, {%0,%1,%2,%3};"
        : "+f"(c[0]), "+f"(c[1]), "+f"(c[2]), "+f"(c[3])
        : "r"(a0), "r"(a1), "r"(a2), "r"(a3), "r"(b0), "r"(b1));
}
__device__ __forceinline__ void ldsm4(unsigned r[4], uint32_t addr) {
    asm volatile("ldmatrix.sync.aligned.m8n8.x4.shared.b16 {%0,%1,%2,%3}, [%4];"
        : "=r"(r[0]), "=r"(r[1]), "=r"(r[2]), "=r"(r[3]) : "r"(addr));
}

// ---------------------------------------------------------------------------
// SMEM: 3 stages, K-chunk 64 halves. A/B tiles 128 x 64 halves, stride 72.
// ---------------------------------------------------------------------------
#define STAGES 3
#define KC    64
#define HSTR  72
#define ROWB  (HSTR * 2)                  // 144 bytes per row
#define A_BYTES (128 * ROWB)              // 18432
#define B_OFF   A_BYTES
#define B_BYTES (128 * ROWB)              // 18432
#define STAGE   (A_BYTES + B_BYTES)       // 36864
#define SMEM_BYTES (STAGES * STAGE)       // 110592 per CTA (x2 CTAs = 221184)

__device__ __forceinline__ void load_tile(const __half* __restrict__ src, size_t gstr,
                                          uint32_t dst, int tid) {
#pragma unroll
    for (int q = 0; q < 4; q++) {
        int idx = tid + q * NT;
        int row = idx >> 3, seg = idx & 7;
        CP_ASYNC16(dst + row * ROWB + seg * 16, src + (size_t)row * gstr + seg * 8);
    }
}

__device__ __forceinline__ void compute_chunk(uint32_t sA, uint32_t sB,
                                              uint32_t a_off, uint32_t b_off,
                                              float acc[4][4][4]) {
#pragma unroll
    for (int kk = 0; kk < 4; kk++) {
        unsigned a[4][4], b[2][4];
#pragma unroll
        for (int mf = 0; mf < 4; mf++)
            ldsm4(a[mf], sA + mf * (16 * ROWB) + a_off + kk * 32);
#pragma unroll
        for (int p = 0; p < 2; p++)
            ldsm4(b[p], sB + p * (16 * ROWB) + b_off + kk * 32);
#pragma unroll
        for (int mf = 0; mf < 4; mf++)
#pragma unroll
            for (int p = 0; p < 2; p++) {
                mma_f16(acc[mf][2 * p],     a[mf][0], a[mf][1], a[mf][2], a[mf][3],
                        b[p][0], b[p][1]);
                mma_f16(acc[mf][2 * p + 1], a[mf][0], a[mf][1], a[mf][2], a[mf][3],
                        b[p][2], b[p][3]);
            }
    }
}

// ---------------------------------------------------------------------------
// Prep kernels
// ---------------------------------------------------------------------------
__global__ void half_copy(const float* __restrict__ src, __half* __restrict__ dst) {
    size_t i = ((size_t)blockIdx.x * 256 + threadIdx.x) * 8;
    float4 v0 = *(const float4*)(src + i);
    float4 v1 = *(const float4*)(src + i + 4);
    __half2 h[4] = { __floats2half2_rn(v0.x, v0.y), __floats2half2_rn(v0.z, v0.w),
                     __floats2half2_rn(v1.x, v1.y), __floats2half2_rn(v1.z, v1.w) };
    *(uint4*)(dst + i) = *(uint4*)h;
}
__global__ void wdec_T(const float* __restrict__ W_dec) {
    int p = blockIdx.z;
    int j = 0, a = 0;
    while (a + j + 1 <= p) { a += j + 1; ++j; }
    int i = p - a;
    int f0 = blockIdx.x * 32, d0 = blockIdx.y * 32;
    int tx = threadIdx.x, ty = threadIdx.y;
    __shared__ float t[32][33];
    const float* src = W_dec + (size_t)(i * NL + j) * FT * DM;
#pragma unroll
    for (int r = 0; r < 4; r++)
        t[ty + r * 8][tx] = src[(size_t)(f0 + ty + r * 8) * DM + d0 + tx];
    __syncthreads();
    __half* dst = g_wdT + (size_t)p * DM * FT;
#pragma unroll
    for (int r = 0; r < 4; r++)
        dst[(size_t)(d0 + ty + r * 8) * FT + f0 + tx] = __float2half_rn(t[tx][ty + r * 8]);
}

// ---------------------------------------------------------------------------
// Encoder. grid (FT/128, NPOS/128, NL). Also zeroes the pair counters.
// ---------------------------------------------------------------------------
__global__ __launch_bounds__(NT, 2)
void encode_tc(const float* __restrict__ b_enc) {
    extern __shared__ float smem[];
    if (blockIdx.x == 0 && blockIdx.y == 0 && blockIdx.z == 0 && threadIdx.x < NPAIR)
        g_pair_done[threadIdx.x] = 0;

    const int l = blockIdx.z, m0 = blockIdx.y * 128, n0 = blockIdx.x * 128;
    const int tid = threadIdx.x, lane = tid & 31, warp = tid >> 5;
    const int wm = warp & 1, wn = warp >> 1;
    const uint32_t sb = smem_u32(smem);

    const uint32_t a_off = (wm * 64 + (lane & 15)) * ROWB + (lane >> 4) * 16;
    const uint32_t b_off = (wn * 32 + (lane & 7) + ((lane >> 4) << 3)) * ROWB
                         + ((lane >> 3) & 1) * 16;

    float acc[4][4][4];
#pragma unroll
    for (int a = 0; a < 4; a++)
#pragma unroll
        for (int b = 0; b < 4; b++)
#pragma unroll
            for (int c = 0; c < 4; c++) acc[a][b][c] = 0.f;

    const __half* abase = g_xr  + ((size_t)l * NPOS + m0) * DM;
    const __half* bbase = g_wer + ((size_t)l * FT + n0) * DM;
    const int NC = DM / KC;

    load_tile(abase, DM, sb, tid);
    load_tile(bbase, DM, sb + B_OFF, tid);
    CP_COMMIT();
    load_tile(abase + KC, DM, sb + STAGE, tid);
    load_tile(bbase + KC, DM, sb + STAGE + B_OFF, tid);
    CP_COMMIT();

    for (int c = 0; c < NC; c++) {
        if (c + 1 < NC) { CP_WAIT1(); } else { CP_WAIT0(); }
        __syncthreads();
        int nc = c + 2;
        if (nc < NC) {
            uint32_t s = sb + (nc % STAGES) * STAGE;
            load_tile(abase + nc * KC, DM, s, tid);
            load_tile(bbase + nc * KC, DM, s + B_OFF, tid);
            CP_COMMIT();
        }
        uint32_t st = sb + (c % STAGES) * STAGE;
        compute_chunk(st, st + B_OFF, a_off, b_off, acc);
    }

    const float* be = b_enc + (size_t)l * FT + n0;
#pragma unroll
    for (int mf = 0; mf < 4; mf++) {
        int r0 = m0 + wm * 64 + mf * 16 + (lane >> 2);
        __half* d0 = g_feats + ((size_t)l * NPOS + r0) * FT + n0;
        __half* d1 = d0 + 8 * FT;
#pragma unroll
        for (int nf = 0; nf < 4; nf++) {
            int c0 = wn * 32 + nf * 8 + (lane & 3) * 2;
            float b0 = be[c0], b1 = be[c0 + 1];
            __half2 v0 = __floats2half2_rn(fmaxf(acc[mf][nf][0] + b0, 0.f),
                                           fmaxf(acc[mf][nf][1] + b1, 0.f));
            __half2 v1 = __floats2half2_rn(fmaxf(acc[mf][nf][2] + b0, 0.f),
                                           fmaxf(acc[mf][nf][3] + b1, 0.f));
            *(__half2*)(d0 + c0) = v0;
            *(__half2*)(d1 + c0) = v1;
        }
    }
}

// ---------------------------------------------------------------------------
// Fused decode + reduce. 1D grid of 1728 decode CTAs then 6144 reduce CTAs.
// Decode CTAs signal per-pair completion; reduce CTAs (later indices, same
// grid => producers dispatched first => no deadlock) wait then sum.
// ---------------------------------------------------------------------------
#define DEC_CTAS (NPAIR * 48)                 // 1728
#define RED_PER_J (NPOS * DM / 1024)          // 768
#define RED_CTAS (NL * RED_PER_J)             // 6144

__global__ __launch_bounds__(NT, 2)
void decode_reduce(const float* __restrict__ b_dec, float* __restrict__ out) {
    extern __shared__ float smem[];
    const int bid = blockIdx.x;
    const int tid = threadIdx.x;

    if (bid < DEC_CTAS) {
        // ---------------- decode path ----------------
        const int p = bid / 48, sub = bid % 48;
        const int m0 = (sub / 6) * 128, n0 = (sub % 6) * 128;
        int j = 0, a0 = 0;
        while (a0 + j + 1 <= p) { a0 += j + 1; ++j; }
        const int i = p - a0;
        const int lane = tid & 31, warp = tid >> 5;
        const int wm = warp & 1, wn = warp >> 1;
        const uint32_t sb = smem_u32(smem);

        const uint32_t a_off = (wm * 64 + (lane & 15)) * ROWB + (lane >> 4) * 16;
        const uint32_t b_off = (wn * 32 + (lane & 7) + ((lane >> 4) << 3)) * ROWB
                             + ((lane >> 3) & 1) * 16;

        float acc[4][4][4];
#pragma unroll
        for (int a = 0; a < 4; a++)
#pragma unroll
            for (int b = 0; b < 4; b++)
#pragma unroll
                for (int c = 0; c < 4; c++) acc[a][b][c] = 0.f;

        const __half* abase = g_feats + ((size_t)i * NPOS + m0) * FT;
        const __half* bbase = g_wdT + (size_t)p * DM * FT + (size_t)n0 * FT;
        const int NC = FT / KC;

        load_tile(abase, FT, sb, tid);
        load_tile(bbase, FT, sb + B_OFF, tid);
        CP_COMMIT();
        load_tile(abase + KC, FT, sb + STAGE, tid);
        load_tile(bbase + KC, FT, sb + STAGE + B_OFF, tid);
        CP_COMMIT();

        for (int c = 0; c < NC; c++) {
            if (c + 1 < NC) { CP_WAIT1(); } else { CP_WAIT0(); }
            __syncthreads();
            int nc = c + 2;
            if (nc < NC) {
                uint32_t s = sb + (nc % STAGES) * STAGE;
                load_tile(abase + nc * KC, FT, s, tid);
                load_tile(bbase + nc * KC, FT, s + B_OFF, tid);
                CP_COMMIT();
            }
            uint32_t st = sb + (c % STAGES) * STAGE;
            compute_chunk(st, st + B_OFF, a_off, b_off, acc);
        }

#pragma unroll
        for (int mf = 0; mf < 4; mf++) {
            int r0 = m0 + wm * 64 + mf * 16 + (lane >> 2);
            float* d0 = g_part + ((size_t)p * NPOS + r0) * DM + n0;
            float* d1 = d0 + 8 * DM;
#pragma unroll
            for (int nf = 0; nf < 4; nf++) {
                int c0 = wn * 32 + nf * 8 + (lane & 3) * 2;
                float2 v0 = { acc[mf][nf][0], acc[mf][nf][1] };
                float2 v1 = { acc[mf][nf][2], acc[mf][nf][3] };
                *(float2*)(d0 + c0) = v0;
                *(float2*)(d1 + c0) = v1;
            }
        }
        // publish: all stores visible, then bump pair counter
        __threadfence();
        __syncthreads();
        if (tid == 0) atomicAdd(&g_pair_done[p], 1);
    } else {
        // ---------------- reduce path ----------------
        const int r = bid - DEC_CTAS;
        const int jj = r / RED_PER_J;
        const int blk = r % RED_PER_J;
        const int base = jj * (jj + 1) / 2;

        if (tid == 0) {
            for (int i = 0; i <= jj; i++) {
                int* ctr = &g_pair_done[base + i];
                int v;
                do {
                    asm volatile("ld.global.acquire.gpu.b32 %0, [%1];" : "=r"(v) : "l"(ctr));
                    if (v < 48) __nanosleep(256);
                } while (v < 48);
            }
        }
        __syncthreads();

        size_t lin = ((size_t)blk * 256 + tid) * 4;
        int d = (int)(lin % DM);
        float4 acc = *(const float4*)(b_dec + (size_t)jj * DM + d);
        for (int i = 0; i <= jj; i++) {
            float4 v = *(const float4*)(g_part + (size_t)(base + i) * NPOS * DM + lin);
            acc.x += v.x; acc.y += v.y; acc.z += v.z; acc.w += v.w;
        }
        *(float4*)(out + (size_t)jj * NPOS * DM + lin) = acc;
    }
}

// ---------------------------------------------------------------------------
extern "C" void kernel_launch(void* const* d_in, const int* in_sizes, int n_in,
                              void* d_out, int out_size) {
    const float* x     = (const float*)d_in[0];
    const float* W_enc = (const float*)d_in[1];
    const float* b_enc = (const float*)d_in[2];
    const float* W_dec = (const float*)d_in[3];
    const float* b_dec = (const float*)d_in[4];
    float* out = (float*)d_out;

    static cudaStream_t s2 = nullptr;
    static cudaEvent_t evA = nullptr, evB = nullptr;
    if (!s2) {
        cudaFuncSetAttribute(encode_tc, cudaFuncAttributeMaxDynamicSharedMemorySize, SMEM_BYTES);
        cudaFuncSetAttribute(decode_reduce, cudaFuncAttributeMaxDynamicSharedMemorySize, SMEM_BYTES);
        cudaStreamCreateWithFlags(&s2, cudaStreamNonBlocking);
        cudaEventCreateWithFlags(&evA, cudaEventDisableTiming);
        cudaEventCreateWithFlags(&evB, cudaEventDisableTiming);
    }

    __half* g_xr_p;   cudaGetSymbolAddress((void**)&g_xr_p,  g_xr);
    __half* g_wer_p;  cudaGetSymbolAddress((void**)&g_wer_p, g_wer);

    // Fork: W_dec transpose+convert on side stream, overlapped with encode chain.
    cudaEventRecord(evA, 0);
    cudaStreamWaitEvent(s2, evA, 0);
    wdec_T<<<dim3(FT / 32, DM / 32, NPAIR), dim3(32, 8), 0, s2>>>(W_dec);
    cudaEventRecord(evB, s2);

    half_copy<<<(NL * NPOS * DM) / 2048, 256>>>(x, g_xr_p);
    half_copy<<<(NL * FT * DM) / 2048, 256>>>(W_enc, g_wer_p);
    encode_tc<<<dim3(FT / 128, NPOS / 128, NL), NT, SMEM_BYTES>>>(b_enc);

    // Join, then fused decode + reduce.
    cudaStreamWaitEvent(0, evB, 0);
    decode_reduce<<<DEC_CTAS + RED_CTAS, NT, SMEM_BYTES>>>(b_dec, out);
}